// round 10
// baseline (speedup 1.0000x reference)
#include <cuda_runtime.h>
#include <cuda_fp16.h>

#define SS 1024
#define DD 512
#define HH 8
#define BBB 8
#define NQ (BBB*SS)
#define GP  72        // smem pitch in fp16 halves (144B rows -> conflict-free ldmatrix)
#define GPB 144

__device__ float g_Q[NQ*DD];
__device__ float g_K[NQ*DD];
__device__ float g_V[NQ*DD];
__device__ float g_X[NQ*DD];

// ---------------------------------------------------------------------------
__device__ __forceinline__ unsigned s2u(const void* p) {
    unsigned a;
    asm("{ .reg .u64 t; cvta.to.shared.u64 t, %1; cvt.u32.u64 %0, t; }" : "=r"(a) : "l"(p));
    return a;
}
__device__ __forceinline__ unsigned pack2h(float x0, float x1) {
    unsigned r;
    asm("cvt.rn.f16x2.f32 %0, %1, %2;" : "=r"(r) : "f"(x1), "f"(x0)); // low16=f16(x0)
    return r;
}
__device__ __forceinline__ void mma_f16(float c[4], unsigned a0, unsigned a1,
                                        unsigned a2, unsigned a3,
                                        unsigned b0, unsigned b1) {
    asm volatile("mma.sync.aligned.m16n8k16.row.col.f32.f16.f16.f32 "
        "{%0,%1,%2,%3}, {%4,%5,%6,%7}, {%8,%9}, {%0,%1,%2,%3};"
        : "+f"(c[0]), "+f"(c[1]), "+f"(c[2]), "+f"(c[3])
        : "r"(a0), "r"(a1), "r"(a2), "r"(a3), "r"(b0), "r"(b1));
}
__device__ __forceinline__ void ldm4(unsigned* r, unsigned addr) {
    asm volatile("ldmatrix.sync.aligned.m8n8.x4.shared.b16 {%0,%1,%2,%3}, [%4];"
        : "=r"(r[0]), "=r"(r[1]), "=r"(r[2]), "=r"(r[3]) : "r"(addr));
}
__device__ __forceinline__ void ldm4t(unsigned* r, unsigned addr) {
    asm volatile("ldmatrix.sync.aligned.m8n8.x4.trans.shared.b16 {%0,%1,%2,%3}, [%4];"
        : "=r"(r[0]), "=r"(r[1]), "=r"(r[2]), "=r"(r[3]) : "r"(addr));
}
// f32x4 -> fp16x4, one 8B store at [r][cbyte], pitch GPB
__device__ __forceinline__ void sts_h(char* base, int r, int cbyte, float4 v) {
    *(uint2*)(base + r*GPB + cbyte) = make_uint2(pack2h(v.x, v.y), pack2h(v.z, v.w));
}

// ===========================================================================
// GEMM: C[8192,512] = A[8192,512] @ W[512,512]^T (+bias)
// CTA 128x128, 8 warps 4(M)x2(N), warp tile 32x64, k-chunks of 64, fp16.
// ===========================================================================
#define G_AH 0
#define G_WH 18432
#define G_SM 36864

__global__ __launch_bounds__(256, 2) void gemm_mma(
    const float* __restrict__ A, const float* __restrict__ W,
    const float* __restrict__ bias, float* __restrict__ C)
{
    extern __shared__ char sm[];
    char* AH = sm + G_AH;
    char* WH = sm + G_WH;
    const unsigned sb = s2u(sm);
    const int tid = threadIdx.x, lane = tid & 31, wid = tid >> 5;
    const int wm = wid & 3, wn = wid >> 2;
    const int g = lane >> 2, cq = lane & 3;
    const int m0 = blockIdx.y * 128, n0 = blockIdx.x * 128;

    const int aRow = lane & 15, aCol = (lane >> 4) << 3;
    const int bRow = (lane & 7) + ((lane >> 4) << 3), bCol = ((lane >> 3) & 1) << 3;
    const unsigned aH0 = sb + G_AH + ((wm*32 + aRow)*GP + aCol)*2, dA = 16*GPB;
    const unsigned wH0 = sb + G_WH + ((wn*64 + bRow)*GP + bCol)*2;

    float acc[2][8][4] = {};

    for (int kc = 0; kc < 8; ++kc) {
        const int k0 = kc * 64;
        #pragma unroll
        for (int u = 0; u < 8; ++u) {               // A tile 128x64 f32
            int idx = tid + u * 256, rr = idx >> 4, c4 = idx & 15;
            float4 v = *(const float4*)(A + (size_t)(m0 + rr) * DD + k0 + c4 * 4);
            sts_h(AH, rr, c4 * 8, v);
        }
        #pragma unroll
        for (int u = 0; u < 8; ++u) {               // W tile 128x64 f32
            int idx = tid + u * 256, rr = idx >> 4, c4 = idx & 15;
            float4 v = *(const float4*)(W + (size_t)(n0 + rr) * DD + k0 + c4 * 4);
            sts_h(WH, rr, c4 * 8, v);
        }
        __syncthreads();
        #pragma unroll
        for (int kk = 0; kk < 4; ++kk) {
            const unsigned ko2 = kk * 32;
            unsigned a[8], b[16];
            ldm4(a,     aH0 + ko2); ldm4(a + 4, aH0 + dA + ko2);
            #pragma unroll
            for (int nb = 0; nb < 4; ++nb)
                ldm4(b + 4*nb, wH0 + nb*dA + ko2);
            #pragma unroll
            for (int mt = 0; mt < 2; ++mt) {
                unsigned* ap = a + mt * 4;
                #pragma unroll
                for (int nt = 0; nt < 8; ++nt)
                    mma_f16(acc[mt][nt], ap[0], ap[1], ap[2], ap[3], b[2*nt], b[2*nt+1]);
            }
        }
        __syncthreads();
    }
    #pragma unroll
    for (int mt = 0; mt < 2; ++mt)
        #pragma unroll
        for (int nt = 0; nt < 8; ++nt) {
            int row = m0 + wm * 32 + mt * 16 + g;
            int col = n0 + wn * 64 + nt * 8 + 2 * cq;
            float b0 = bias ? bias[col] : 0.f, b1 = bias ? bias[col + 1] : 0.f;
            *(float2*)(C + (size_t)row * DD + col) =
                make_float2(acc[mt][nt][0] + b0, acc[mt][nt][1] + b1);
            *(float2*)(C + (size_t)(row + 8) * DD + col) =
                make_float2(acc[mt][nt][2] + b0, acc[mt][nt][3] + b1);
        }
}

// ===========================================================================
// Attention: CTA=(h, qtile 128, b). Flash, no-max softmax, fp16.
// Warps 4(Mq)x2(Nk), warp tile 32x32. V natural [k][d]; P.V via ldmatrix.trans.
// ===========================================================================
#define A_QH 0             // 128 x GP fp16 = 18432
#define A_KH 18432         // 64 x GP = 9216
#define A_VH 27648         // 9216
#define A_LS 36864         // float[2][128]
#define A_LI 37888         // float[128]
#define A_SM 38400
#define OPITCH 68          // OSM float pitch (reuses Q/K/V region: 128*68*4=34816)

__global__ __launch_bounds__(256, 2) void attn_mma(
    const float* __restrict__ Q, const float* __restrict__ K,
    const float* __restrict__ V, const float* __restrict__ gprob,
    const int* __restrict__ mask, float* __restrict__ X)
{
    extern __shared__ char sm[];
    char* QH = sm + A_QH;
    char* KH = sm + A_KH;
    char* VH = sm + A_VH;
    float* LSM = (float*)(sm + A_LS);
    float* LIS = (float*)(sm + A_LI);
    float* OSM = (float*)sm;                   // reused after mainloop
    const unsigned sb = s2u(sm);

    const int tid = threadIdx.x, lane = tid & 31, wid = tid >> 5;
    const int wm = wid & 3, wn = wid >> 2;
    const int g = lane >> 2, cq = lane & 3;
    const int h = blockIdx.x, qt = blockIdx.y, b = blockIdx.z;
    const int q0 = qt * 128;

    const int aRow = lane & 15, aCol = (lane >> 4) << 3;
    const int bRow = (lane & 7) + ((lane >> 4) << 3), bCol = ((lane >> 3) & 1) << 3;
    const unsigned qHa = sb + A_QH + ((wm*32 + aRow)*GP + aCol)*2, dA = 16*GPB;
    const unsigned kH0 = sb + A_KH + ((wn*32 + bRow)*GP + bCol)*2, dK = 16*GPB;
    const unsigned vHa = sb + A_VH + ((wn*32 + aRow)*GP + aCol)*2; // rows = k

    const float* Qb = Q + (size_t)b * SS * DD + h * 64;
    const float* Kb = K + (size_t)b * SS * DD + h * 64;
    const float* Vb = V + (size_t)b * SS * DD + h * 64;

    #pragma unroll
    for (int u = 0; u < 8; ++u) {               // Q tile 128x64
        int idx = tid + u * 256, rr = idx >> 4, c4 = idx & 15;
        float4 v = *(const float4*)(Qb + (size_t)(q0 + rr) * DD + c4 * 4);
        sts_h(QH, rr, c4 * 8, v);
    }

    const int qbase = q0 + wm * 32 + g;         // row of this lane's first q
    const int*   mb = mask  + ((size_t)b * SS + qbase) * SS;
    const float* gb = gprob + ((size_t)b * SS + qbase) * SS;

    float o[2][8][4] = {};
    float ls00 = 0.f, ls01 = 0.f, ls10 = 0.f, ls11 = 0.f;
    __syncthreads();

    for (int kt = 0; kt < 16; ++kt) {
        const int k0 = kt * 64;
        #pragma unroll
        for (int u = 0; u < 4; ++u) {           // K tile 64x64 [kpos][dk]
            int idx = tid + u * 256, rr = idx >> 4, c4 = idx & 15;
            float4 v = *(const float4*)(Kb + (size_t)(k0 + rr) * DD + c4 * 4);
            sts_h(KH, rr, c4 * 8, v);
        }
        #pragma unroll
        for (int u = 0; u < 4; ++u) {           // V tile 64x64 NATURAL [kpos][d]
            int idx = tid + u * 256, rr = idx >> 4, c4 = idx & 15;
            float4 v = *(const float4*)(Vb + (size_t)(k0 + rr) * DD + c4 * 4);
            sts_h(VH, rr, c4 * 8, v);
        }
        __syncthreads();

        // ---- S = Q.K^T (warp tile 32x32) ----
        float s[2][4][4] = {};
        #pragma unroll
        for (int kk = 0; kk < 4; ++kk) {
            const unsigned ko2 = kk * 32;
            unsigned a[8], bh[8];
            ldm4(a,     qHa + ko2); ldm4(a + 4, qHa + dA + ko2);
            ldm4(bh,    kH0 + ko2); ldm4(bh + 4, kH0 + dK + ko2);
            #pragma unroll
            for (int mt = 0; mt < 2; ++mt) {
                unsigned* ap = a + mt * 4;
                #pragma unroll
                for (int nt = 0; nt < 4; ++nt)
                    mma_f16(s[mt][nt], ap[0], ap[1], ap[2], ap[3], bh[2*nt], bh[2*nt+1]);
            }
        }

        // ---- softmax numerator (no max-sub; masked -> exact 0); pack P fp16 ----
        unsigned PHf[2][4][2];
        #pragma unroll
        for (int mt = 0; mt < 2; ++mt) {
            const int qg0 = qbase + mt * 16, qg1 = qg0 + 8;
            const size_t ro0 = (size_t)(mt * 16) * SS, ro1 = ro0 + (size_t)8 * SS;
            float lA = 0.f, lB = 0.f;
            #pragma unroll
            for (int nt = 0; nt < 4; ++nt) {
                const int kg = k0 + wn * 32 + nt * 8 + 2 * cq;
                int2   m0v = *(const int2*)(mb + ro0 + kg);
                int2   m1v = *(const int2*)(mb + ro1 + kg);
                float2 g0v = *(const float2*)(gb + ro0 + kg);
                float2 g1v = *(const float2*)(gb + ro1 + kg);
                float p00 = (m0v.x | (int)(kg     == qg0)) ? __expf(s[mt][nt][0] * 0.125f) : 0.f;
                float p01 = (m0v.y | (int)(kg + 1 == qg0)) ? __expf(s[mt][nt][1] * 0.125f) : 0.f;
                float p10 = (m1v.x | (int)(kg     == qg1)) ? __expf(s[mt][nt][2] * 0.125f) : 0.f;
                float p11 = (m1v.y | (int)(kg + 1 == qg1)) ? __expf(s[mt][nt][3] * 0.125f) : 0.f;
                lA += p00 + p01;
                lB += p10 + p11;
                PHf[mt][nt][0] = pack2h(p00 * g0v.x, p01 * g0v.y);
                PHf[mt][nt][1] = pack2h(p10 * g1v.x, p11 * g1v.y);
            }
            if (mt == 0) { ls00 += lA; ls01 += lB; } else { ls10 += lA; ls11 += lB; }
        }

        // ---- O += P.V ; V B-frags via ldmatrix.trans, shared across mt ----
        #pragma unroll
        for (int kk2 = 0; kk2 < 2; ++kk2) {
            const unsigned kofs = (unsigned)kk2 * 16 * GPB;
            unsigned vh[16];
            #pragma unroll
            for (int dq = 0; dq < 4; ++dq)
                ldm4t(vh + dq * 4, vHa + kofs + dq * 32);
            #pragma unroll
            for (int mt = 0; mt < 2; ++mt) {
                unsigned p0 = PHf[mt][2*kk2][0], p1 = PHf[mt][2*kk2][1];
                unsigned p2 = PHf[mt][2*kk2+1][0], p3 = PHf[mt][2*kk2+1][1];
                #pragma unroll
                for (int dn = 0; dn < 8; ++dn)
                    mma_f16(o[mt][dn], p0, p1, p2, p3, vh[2*dn], vh[2*dn+1]);
            }
        }
        __syncthreads();
    }

    // ---- epilogue: l reduce, O combine across wn, write out ----
    ls00 += __shfl_xor_sync(0xFFFFFFFFu, ls00, 1); ls00 += __shfl_xor_sync(0xFFFFFFFFu, ls00, 2);
    ls01 += __shfl_xor_sync(0xFFFFFFFFu, ls01, 1); ls01 += __shfl_xor_sync(0xFFFFFFFFu, ls01, 2);
    ls10 += __shfl_xor_sync(0xFFFFFFFFu, ls10, 1); ls10 += __shfl_xor_sync(0xFFFFFFFFu, ls10, 2);
    ls11 += __shfl_xor_sync(0xFFFFFFFFu, ls11, 1); ls11 += __shfl_xor_sync(0xFFFFFFFFu, ls11, 2);
    if (cq == 0) {
        int r = wm * 32 + g;
        LSM[wn * 128 + r]      = ls00;
        LSM[wn * 128 + r + 8]  = ls01;
        LSM[wn * 128 + r + 16] = ls10;
        LSM[wn * 128 + r + 24] = ls11;
    }
    __syncthreads();
    if (tid < 128) LIS[tid] = 1.0f / (LSM[tid] + LSM[128 + tid]);
    if (wn == 0) {
        #pragma unroll
        for (int mt = 0; mt < 2; ++mt)
            #pragma unroll
            for (int dn = 0; dn < 8; ++dn) {
                int r0 = wm * 32 + mt * 16 + g, col = dn * 8 + 2 * cq;
                *(float2*)(OSM + r0 * OPITCH + col)       = make_float2(o[mt][dn][0], o[mt][dn][1]);
                *(float2*)(OSM + (r0 + 8) * OPITCH + col) = make_float2(o[mt][dn][2], o[mt][dn][3]);
            }
    }
    __syncthreads();
    if (wn == 1) {
        #pragma unroll
        for (int mt = 0; mt < 2; ++mt)
            #pragma unroll
            for (int dn = 0; dn < 8; ++dn) {
                int r0 = wm * 32 + mt * 16 + g, col = dn * 8 + 2 * cq;
                float2* p0 = (float2*)(OSM + r0 * OPITCH + col);
                float2* p1 = (float2*)(OSM + (r0 + 8) * OPITCH + col);
                p0->x += o[mt][dn][0]; p0->y += o[mt][dn][1];
                p1->x += o[mt][dn][2]; p1->y += o[mt][dn][3];
            }
    }
    __syncthreads();
    #pragma unroll
    for (int u = 0; u < 8; ++u) {
        int idx = tid + u * 256, rr = idx >> 4, c4 = idx & 15;
        float li = LIS[rr];
        float4 vv = *(float4*)(OSM + rr * OPITCH + c4 * 4);
        vv.x *= li; vv.y *= li; vv.z *= li; vv.w *= li;
        *(float4*)(X + ((size_t)b * SS + q0 + rr) * DD + h * 64 + c4 * 4) = vv;
    }
}

// ===========================================================================
extern "C" void kernel_launch(void* const* d_in, const int* in_sizes, int n_in,
                              void* d_out, int out_size)
{
    const float* query = (const float*)d_in[0];
    const float* key   = (const float*)d_in[1];
    const float* value = (const float*)d_in[2];
    const float* gprob = (const float*)d_in[3];
    const float* Wq    = (const float*)d_in[4];
    const float* Wk    = (const float*)d_in[5];
    const float* Wv    = (const float*)d_in[6];
    const float* Wh    = (const float*)d_in[7];
    const float* bh    = (const float*)d_in[8];
    const int*   mask  = (const int*)d_in[9];
    float* out = (float*)d_out;

    float *Qp, *Kp, *Vp, *Xp;
    cudaGetSymbolAddress((void**)&Qp, g_Q);
    cudaGetSymbolAddress((void**)&Kp, g_K);
    cudaGetSymbolAddress((void**)&Vp, g_V);
    cudaGetSymbolAddress((void**)&Xp, g_X);

    cudaFuncSetAttribute(gemm_mma, cudaFuncAttributeMaxDynamicSharedMemorySize, G_SM);
    cudaFuncSetAttribute(attn_mma, cudaFuncAttributeMaxDynamicSharedMemorySize, A_SM);

    dim3 blk(256);
    dim3 pg(DD / 128, NQ / 128);                // (4, 64)
    gemm_mma<<<pg, blk, G_SM>>>(query, Wq, nullptr, Qp);
    gemm_mma<<<pg, blk, G_SM>>>(key,   Wk, nullptr, Kp);
    gemm_mma<<<pg, blk, G_SM>>>(value, Wv, nullptr, Vp);
    attn_mma<<<dim3(HH, SS / 128, BBB), blk, A_SM>>>(Qp, Kp, Vp, gprob, mask, Xp);
    gemm_mma<<<pg, blk, G_SM>>>(Xp, Wh, bh, out);
}

// round 11
// speedup vs baseline: 1.2567x; 1.2567x over previous
#include <cuda_runtime.h>
#include <cuda_fp16.h>

#define SS 1024
#define DD 512
#define HH 8
#define BBB 8
#define NQ (BBB*SS)
#define GP  72        // smem pitch in fp16 halves (144B rows -> conflict-free ldmatrix)
#define GPB 144

__device__ float g_Q[NQ*DD];
__device__ float g_K[NQ*DD];
__device__ float g_V[NQ*DD];
__device__ float g_X[NQ*DD];

// ---------------------------------------------------------------------------
__device__ __forceinline__ unsigned s2u(const void* p) {
    unsigned a;
    asm("{ .reg .u64 t; cvta.to.shared.u64 t, %1; cvt.u32.u64 %0, t; }" : "=r"(a) : "l"(p));
    return a;
}
__device__ __forceinline__ unsigned pack2h(float x0, float x1) {
    unsigned r;
    asm("cvt.rn.f16x2.f32 %0, %1, %2;" : "=r"(r) : "f"(x1), "f"(x0)); // low16=f16(x0)
    return r;
}
__device__ __forceinline__ void mma_f16(float c[4], unsigned a0, unsigned a1,
                                        unsigned a2, unsigned a3,
                                        unsigned b0, unsigned b1) {
    asm volatile("mma.sync.aligned.m16n8k16.row.col.f32.f16.f16.f32 "
        "{%0,%1,%2,%3}, {%4,%5,%6,%7}, {%8,%9}, {%0,%1,%2,%3};"
        : "+f"(c[0]), "+f"(c[1]), "+f"(c[2]), "+f"(c[3])
        : "r"(a0), "r"(a1), "r"(a2), "r"(a3), "r"(b0), "r"(b1));
}
__device__ __forceinline__ void ldm4(unsigned* r, unsigned addr) {
    asm volatile("ldmatrix.sync.aligned.m8n8.x4.shared.b16 {%0,%1,%2,%3}, [%4];"
        : "=r"(r[0]), "=r"(r[1]), "=r"(r[2]), "=r"(r[3]) : "r"(addr));
}
__device__ __forceinline__ void ldm4t(unsigned* r, unsigned addr) {
    asm volatile("ldmatrix.sync.aligned.m8n8.x4.trans.shared.b16 {%0,%1,%2,%3}, [%4];"
        : "=r"(r[0]), "=r"(r[1]), "=r"(r[2]), "=r"(r[3]) : "r"(addr));
}
// f32x4 -> fp16x4, one 8B store at [r][cbyte], pitch GPB
__device__ __forceinline__ void sts_h(char* base, int r, int cbyte, float4 v) {
    *(uint2*)(base + r*GPB + cbyte) = make_uint2(pack2h(v.x, v.y), pack2h(v.z, v.w));
}

// ===========================================================================
// GEMM (R10 config — measured ~115us for 4 launches):
// C[8192,512] = A @ W^T (+bias). CTA 128x128, warps 4(M)x2(N), tile 32x64.
// ===========================================================================
#define G_AH 0
#define G_WH 18432
#define G_SM 36864

__global__ __launch_bounds__(256, 2) void gemm_mma(
    const float* __restrict__ A, const float* __restrict__ W,
    const float* __restrict__ bias, float* __restrict__ C)
{
    extern __shared__ char sm[];
    char* AH = sm + G_AH;
    char* WH = sm + G_WH;
    const unsigned sb = s2u(sm);
    const int tid = threadIdx.x, lane = tid & 31, wid = tid >> 5;
    const int wm = wid & 3, wn = wid >> 2;
    const int g = lane >> 2, cq = lane & 3;
    const int m0 = blockIdx.y * 128, n0 = blockIdx.x * 128;

    const int aRow = lane & 15, aCol = (lane >> 4) << 3;
    const int bRow = (lane & 7) + ((lane >> 4) << 3), bCol = ((lane >> 3) & 1) << 3;
    const unsigned aH0 = sb + G_AH + ((wm*32 + aRow)*GP + aCol)*2, dA = 16*GPB;
    const unsigned wH0 = sb + G_WH + ((wn*64 + bRow)*GP + bCol)*2;

    float acc[2][8][4] = {};

    for (int kc = 0; kc < 8; ++kc) {
        const int k0 = kc * 64;
        #pragma unroll
        for (int u = 0; u < 8; ++u) {               // A tile 128x64 f32
            int idx = tid + u * 256, rr = idx >> 4, c4 = idx & 15;
            float4 v = *(const float4*)(A + (size_t)(m0 + rr) * DD + k0 + c4 * 4);
            sts_h(AH, rr, c4 * 8, v);
        }
        #pragma unroll
        for (int u = 0; u < 8; ++u) {               // W tile 128x64 f32
            int idx = tid + u * 256, rr = idx >> 4, c4 = idx & 15;
            float4 v = *(const float4*)(W + (size_t)(n0 + rr) * DD + k0 + c4 * 4);
            sts_h(WH, rr, c4 * 8, v);
        }
        __syncthreads();
        #pragma unroll
        for (int kk = 0; kk < 4; ++kk) {
            const unsigned ko2 = kk * 32;
            unsigned a[8], b[16];
            ldm4(a,     aH0 + ko2); ldm4(a + 4, aH0 + dA + ko2);
            #pragma unroll
            for (int nb = 0; nb < 4; ++nb)
                ldm4(b + 4*nb, wH0 + nb*dA + ko2);
            #pragma unroll
            for (int mt = 0; mt < 2; ++mt) {
                unsigned* ap = a + mt * 4;
                #pragma unroll
                for (int nt = 0; nt < 8; ++nt)
                    mma_f16(acc[mt][nt], ap[0], ap[1], ap[2], ap[3], b[2*nt], b[2*nt+1]);
            }
        }
        __syncthreads();
    }
    #pragma unroll
    for (int mt = 0; mt < 2; ++mt)
        #pragma unroll
        for (int nt = 0; nt < 8; ++nt) {
            int row = m0 + wm * 32 + mt * 16 + g;
            int col = n0 + wn * 64 + nt * 8 + 2 * cq;
            float b0 = bias ? bias[col] : 0.f, b1 = bias ? bias[col + 1] : 0.f;
            *(float2*)(C + (size_t)row * DD + col) =
                make_float2(acc[mt][nt][0] + b0, acc[mt][nt][1] + b1);
            *(float2*)(C + (size_t)(row + 8) * DD + col) =
                make_float2(acc[mt][nt][2] + b0, acc[mt][nt][3] + b1);
        }
}

// ===========================================================================
// Attention (R9 config — measured 203.5us): CTA=(h, qtile 64, b).
// Flash, no-max softmax, fp16. Warps 4(Mq)x2(Nk), warp tile 16x32.
// V natural [k][d]; P.V B-frags via ldmatrix.trans.
// ===========================================================================
#define A_QH 0
#define A_KH 9216
#define A_VH 18432
#define A_LS 27648
#define A_LI 28160
#define A_SM 28416
#define OPITCH 68

__global__ __launch_bounds__(256) void attn_mma(
    const float* __restrict__ Q, const float* __restrict__ K,
    const float* __restrict__ V, const float* __restrict__ gprob,
    const int* __restrict__ mask, float* __restrict__ X)
{
    extern __shared__ char sm[];
    char* QH = sm + A_QH;
    char* KH = sm + A_KH;
    char* VH = sm + A_VH;
    float* LSM = (float*)(sm + A_LS);
    float* LIS = (float*)(sm + A_LI);
    float* OSM = (float*)(sm + A_KH);          // reused after mainloop
    const unsigned sb = s2u(sm);

    const int tid = threadIdx.x, lane = tid & 31, wid = tid >> 5;
    const int wm = wid & 3, wn = wid >> 2;
    const int g = lane >> 2, cq = lane & 3;
    const int h = blockIdx.x, qt = blockIdx.y, b = blockIdx.z;
    const int q0 = qt * 64;

    const int aRow = lane & 15, aCol = (lane >> 4) << 3;
    const int bRow = (lane & 7) + ((lane >> 4) << 3), bCol = ((lane >> 3) & 1) << 3;
    const unsigned qHa = sb + A_QH + ((wm*16 + aRow)*GP + aCol)*2;
    const unsigned kH0 = sb + A_KH + ((wn*32 + bRow)*GP + bCol)*2, dK = 16*GPB;
    const unsigned vHa = sb + A_VH + ((wn*32 + aRow)*GP + aCol)*2; // rows = k

    const float* Qb = Q + (size_t)b * SS * DD + h * 64;
    const float* Kb = K + (size_t)b * SS * DD + h * 64;
    const float* Vb = V + (size_t)b * SS * DD + h * 64;

    #pragma unroll
    for (int u = 0; u < 4; ++u) {               // Q tile 64x64
        int idx = tid + u * 256, rr = idx >> 4, c4 = idx & 15;
        float4 v = *(const float4*)(Qb + (size_t)(q0 + rr) * DD + c4 * 4);
        sts_h(QH, rr, c4 * 8, v);
    }

    const int qg0 = q0 + wm * 16 + g, qg1 = qg0 + 8;
    const int*   mr0 = mask  + ((size_t)b * SS + qg0) * SS;
    const int*   mr1 = mask  + ((size_t)b * SS + qg1) * SS;
    const float* gr0 = gprob + ((size_t)b * SS + qg0) * SS;
    const float* gr1 = gprob + ((size_t)b * SS + qg1) * SS;

    float o[8][4] = {};
    float lsum0 = 0.f, lsum1 = 0.f;
    __syncthreads();

    for (int kt = 0; kt < 16; ++kt) {
        const int k0 = kt * 64;
        #pragma unroll
        for (int u = 0; u < 4; ++u) {           // K tile 64x64 [kpos][dk]
            int idx = tid + u * 256, rr = idx >> 4, c4 = idx & 15;
            float4 v = *(const float4*)(Kb + (size_t)(k0 + rr) * DD + c4 * 4);
            sts_h(KH, rr, c4 * 8, v);
        }
        #pragma unroll
        for (int u = 0; u < 4; ++u) {           // V tile 64x64 NATURAL [kpos][d]
            int idx = tid + u * 256, rr = idx >> 4, c4 = idx & 15;
            float4 v = *(const float4*)(Vb + (size_t)(k0 + rr) * DD + c4 * 4);
            sts_h(VH, rr, c4 * 8, v);
        }
        __syncthreads();

        // ---- S = Q.K^T (warp tile 16x32) ----
        float s[4][4] = {};
        #pragma unroll
        for (int kk = 0; kk < 4; ++kk) {
            const unsigned ko2 = kk * 32;
            unsigned aH[4], bh[8];
            ldm4(aH, qHa + ko2);
            ldm4(bh,     kH0 + ko2); ldm4(bh + 4, kH0 + dK + ko2);
            #pragma unroll
            for (int nt = 0; nt < 4; ++nt)
                mma_f16(s[nt], aH[0], aH[1], aH[2], aH[3], bh[2*nt], bh[2*nt+1]);
        }

        // ---- softmax numerator (no max-sub; masked -> exact 0); pack P fp16 ----
        unsigned PHf[4][2];
        #pragma unroll
        for (int nt = 0; nt < 4; ++nt) {
            const int kg = k0 + wn * 32 + nt * 8 + 2 * cq;
            int2   m0v = *(const int2*)(mr0 + kg);
            int2   m1v = *(const int2*)(mr1 + kg);
            float2 g0v = *(const float2*)(gr0 + kg);
            float2 g1v = *(const float2*)(gr1 + kg);
            float p00 = (m0v.x | (int)(kg     == qg0)) ? __expf(s[nt][0] * 0.125f) : 0.f;
            float p01 = (m0v.y | (int)(kg + 1 == qg0)) ? __expf(s[nt][1] * 0.125f) : 0.f;
            float p10 = (m1v.x | (int)(kg     == qg1)) ? __expf(s[nt][2] * 0.125f) : 0.f;
            float p11 = (m1v.y | (int)(kg + 1 == qg1)) ? __expf(s[nt][3] * 0.125f) : 0.f;
            lsum0 += p00 + p01;
            lsum1 += p10 + p11;
            PHf[nt][0] = pack2h(p00 * g0v.x, p01 * g0v.y);
            PHf[nt][1] = pack2h(p10 * g1v.x, p11 * g1v.y);
        }

        // ---- O_partial += P.V ; V B-frags via ldmatrix.trans ----
        #pragma unroll
        for (int kk2 = 0; kk2 < 2; ++kk2) {
            const unsigned kofs = (unsigned)kk2 * 16 * GPB;
            unsigned vh[16];
            #pragma unroll
            for (int dq = 0; dq < 4; ++dq)
                ldm4t(vh + dq * 4, vHa + kofs + dq * 32);
            unsigned p0 = PHf[2*kk2][0], p1 = PHf[2*kk2][1];
            unsigned p2 = PHf[2*kk2+1][0], p3 = PHf[2*kk2+1][1];
            #pragma unroll
            for (int dn = 0; dn < 8; ++dn)
                mma_f16(o[dn], p0, p1, p2, p3, vh[2*dn], vh[2*dn+1]);
        }
        __syncthreads();
    }

    // ---- epilogue: l reduce, O combine across wn, write out ----
    lsum0 += __shfl_xor_sync(0xFFFFFFFFu, lsum0, 1);
    lsum0 += __shfl_xor_sync(0xFFFFFFFFu, lsum0, 2);
    lsum1 += __shfl_xor_sync(0xFFFFFFFFu, lsum1, 1);
    lsum1 += __shfl_xor_sync(0xFFFFFFFFu, lsum1, 2);
    if (cq == 0) {
        LSM[wn * 64 + wm * 16 + g]     = lsum0;
        LSM[wn * 64 + wm * 16 + g + 8] = lsum1;
    }
    __syncthreads();
    if (tid < 64) LIS[tid] = 1.0f / (LSM[tid] + LSM[64 + tid]);
    if (wn == 0) {
        #pragma unroll
        for (int dn = 0; dn < 8; ++dn) {
            int r0 = wm * 16 + g, col = dn * 8 + 2 * cq;
            *(float2*)(OSM + r0 * OPITCH + col)       = make_float2(o[dn][0], o[dn][1]);
            *(float2*)(OSM + (r0 + 8) * OPITCH + col) = make_float2(o[dn][2], o[dn][3]);
        }
    }
    __syncthreads();
    if (wn == 1) {
        #pragma unroll
        for (int dn = 0; dn < 8; ++dn) {
            int r0 = wm * 16 + g, col = dn * 8 + 2 * cq;
            float2* p0 = (float2*)(OSM + r0 * OPITCH + col);
            float2* p1 = (float2*)(OSM + (r0 + 8) * OPITCH + col);
            p0->x += o[dn][0]; p0->y += o[dn][1];
            p1->x += o[dn][2]; p1->y += o[dn][3];
        }
    }
    __syncthreads();
    #pragma unroll
    for (int u = 0; u < 4; ++u) {
        int idx = tid + u * 256, rr = idx >> 4, c4 = idx & 15;
        float li = LIS[rr];
        float4 vv = *(float4*)(OSM + rr * OPITCH + c4 * 4);
        vv.x *= li; vv.y *= li; vv.z *= li; vv.w *= li;
        *(float4*)(X + ((size_t)b * SS + q0 + rr) * DD + h * 64 + c4 * 4) = vv;
    }
}

// ===========================================================================
extern "C" void kernel_launch(void* const* d_in, const int* in_sizes, int n_in,
                              void* d_out, int out_size)
{
    const float* query = (const float*)d_in[0];
    const float* key   = (const float*)d_in[1];
    const float* value = (const float*)d_in[2];
    const float* gprob = (const float*)d_in[3];
    const float* Wq    = (const float*)d_in[4];
    const float* Wk    = (const float*)d_in[5];
    const float* Wv    = (const float*)d_in[6];
    const float* Wh    = (const float*)d_in[7];
    const float* bh    = (const float*)d_in[8];
    const int*   mask  = (const int*)d_in[9];
    float* out = (float*)d_out;

    float *Qp, *Kp, *Vp, *Xp;
    cudaGetSymbolAddress((void**)&Qp, g_Q);
    cudaGetSymbolAddress((void**)&Kp, g_K);
    cudaGetSymbolAddress((void**)&Vp, g_V);
    cudaGetSymbolAddress((void**)&Xp, g_X);

    cudaFuncSetAttribute(gemm_mma, cudaFuncAttributeMaxDynamicSharedMemorySize, G_SM);
    cudaFuncSetAttribute(attn_mma, cudaFuncAttributeMaxDynamicSharedMemorySize, A_SM);

    dim3 blk(256);
    dim3 pg(DD / 128, NQ / 128);                // (4, 64)
    gemm_mma<<<pg, blk, G_SM>>>(query, Wq, nullptr, Qp);
    gemm_mma<<<pg, blk, G_SM>>>(key,   Wk, nullptr, Kp);
    gemm_mma<<<pg, blk, G_SM>>>(value, Wv, nullptr, Vp);
    attn_mma<<<dim3(HH, SS / 64, BBB), blk, A_SM>>>(Qp, Kp, Vp, gprob, mask, Xp);
    gemm_mma<<<pg, blk, G_SM>>>(Xp, Wh, bh, out);
}

// round 12
// speedup vs baseline: 1.3150x; 1.0464x over previous
#include <cuda_runtime.h>
#include <cuda_fp16.h>

#define SS 1024
#define DD 512
#define HH 8
#define BBB 8
#define NQ (BBB*SS)
#define ND (NQ*DD)
#define GP  72        // smem pitch in fp16 halves (144B rows -> conflict-free ldmatrix)
#define GPB 144

// fp16 scratch: projected Q,K,V and attention output X
__device__ __half g_Qh[ND];
__device__ __half g_Kh[ND];
__device__ __half g_Vh[ND];
__device__ __half g_Xh[ND];

// ---------------------------------------------------------------------------
__device__ __forceinline__ unsigned s2u(const void* p) {
    unsigned a;
    asm("{ .reg .u64 t; cvta.to.shared.u64 t, %1; cvt.u32.u64 %0, t; }" : "=r"(a) : "l"(p));
    return a;
}
__device__ __forceinline__ unsigned pack2h(float x0, float x1) {
    unsigned r;
    asm("cvt.rn.f16x2.f32 %0, %1, %2;" : "=r"(r) : "f"(x1), "f"(x0)); // low16=f16(x0)
    return r;
}
__device__ __forceinline__ void mma_f16(float c[4], unsigned a0, unsigned a1,
                                        unsigned a2, unsigned a3,
                                        unsigned b0, unsigned b1) {
    asm volatile("mma.sync.aligned.m16n8k16.row.col.f32.f16.f16.f32 "
        "{%0,%1,%2,%3}, {%4,%5,%6,%7}, {%8,%9}, {%0,%1,%2,%3};"
        : "+f"(c[0]), "+f"(c[1]), "+f"(c[2]), "+f"(c[3])
        : "r"(a0), "r"(a1), "r"(a2), "r"(a3), "r"(b0), "r"(b1));
}
__device__ __forceinline__ void ldm4(unsigned* r, unsigned addr) {
    asm volatile("ldmatrix.sync.aligned.m8n8.x4.shared.b16 {%0,%1,%2,%3}, [%4];"
        : "=r"(r[0]), "=r"(r[1]), "=r"(r[2]), "=r"(r[3]) : "r"(addr));
}
__device__ __forceinline__ void ldm4t(unsigned* r, unsigned addr) {
    asm volatile("ldmatrix.sync.aligned.m8n8.x4.trans.shared.b16 {%0,%1,%2,%3}, [%4];"
        : "=r"(r[0]), "=r"(r[1]), "=r"(r[2]), "=r"(r[3]) : "r"(addr));
}
__device__ __forceinline__ void cpa16(unsigned dst, const void* src) {
    asm volatile("cp.async.cg.shared.global [%0], [%1], 16;" :: "r"(dst), "l"(src));
}
#define CP_COMMIT() asm volatile("cp.async.commit_group;" ::: "memory")
#define CP_WAIT(n)  asm volatile("cp.async.wait_group %0;" :: "n"(n) : "memory")
// f32x4 -> fp16x4, one 8B store at [r][cbyte], pitch GPB
__device__ __forceinline__ void sts_h(char* base, int r, int cbyte, float4 v) {
    *(uint2*)(base + r*GPB + cbyte) = make_uint2(pack2h(v.x, v.y), pack2h(v.z, v.w));
}

// ===========================================================================
// GEMM: C[8192,512] = A @ W^T (+bias). CTA 128x128, warps 4(M)x2(N), tile 32x64.
// A16: A is fp16 (cp.async path). Output: f32+bias (Cf) or fp16 (Ch).
// ===========================================================================
#define G_AH 0
#define G_WH 18432
#define G_SM 36864

template<bool A16>
__global__ __launch_bounds__(256, 2) void gemm_mma(
    const float* __restrict__ Af, const __half* __restrict__ Ah16,
    const float* __restrict__ W, const float* __restrict__ bias,
    float* __restrict__ Cf, __half* __restrict__ Ch)
{
    extern __shared__ char sm[];
    char* AH = sm + G_AH;
    char* WH = sm + G_WH;
    const unsigned sb = s2u(sm);
    const int tid = threadIdx.x, lane = tid & 31, wid = tid >> 5;
    const int wm = wid & 3, wn = wid >> 2;
    const int g = lane >> 2, cq = lane & 3;
    const int m0 = blockIdx.y * 128, n0 = blockIdx.x * 128;

    const int aRow = lane & 15, aCol = (lane >> 4) << 3;
    const int bRow = (lane & 7) + ((lane >> 4) << 3), bCol = ((lane >> 3) & 1) << 3;
    const unsigned aH0 = sb + G_AH + ((wm*32 + aRow)*GP + aCol)*2, dA = 16*GPB;
    const unsigned wH0 = sb + G_WH + ((wn*64 + bRow)*GP + bCol)*2;

    float acc[2][8][4] = {};

    for (int kc = 0; kc < 8; ++kc) {
        const int k0 = kc * 64;
        if (A16) {
            #pragma unroll
            for (int u = 0; u < 4; ++u) {           // A tile 128x64 fp16: 1024 x 16B
                int c = tid + u * 256, row = c >> 3, off = c & 7;
                cpa16(sb + G_AH + row*GPB + off*16,
                      Ah16 + (size_t)(m0 + row) * DD + k0 + off * 8);
            }
        } else {
            #pragma unroll
            for (int u = 0; u < 8; ++u) {           // A tile 128x64 f32
                int idx = tid + u * 256, rr = idx >> 4, c4 = idx & 15;
                float4 v = *(const float4*)(Af + (size_t)(m0 + rr) * DD + k0 + c4 * 4);
                sts_h(AH, rr, c4 * 8, v);
            }
        }
        #pragma unroll
        for (int u = 0; u < 8; ++u) {               // W tile 128x64 f32
            int idx = tid + u * 256, rr = idx >> 4, c4 = idx & 15;
            float4 v = *(const float4*)(W + (size_t)(n0 + rr) * DD + k0 + c4 * 4);
            sts_h(WH, rr, c4 * 8, v);
        }
        if (A16) { CP_COMMIT(); CP_WAIT(0); }
        __syncthreads();
        #pragma unroll
        for (int kk = 0; kk < 4; ++kk) {
            const unsigned ko2 = kk * 32;
            unsigned a[8], b[16];
            ldm4(a,     aH0 + ko2); ldm4(a + 4, aH0 + dA + ko2);
            #pragma unroll
            for (int nb = 0; nb < 4; ++nb)
                ldm4(b + 4*nb, wH0 + nb*dA + ko2);
            #pragma unroll
            for (int mt = 0; mt < 2; ++mt) {
                unsigned* ap = a + mt * 4;
                #pragma unroll
                for (int nt = 0; nt < 8; ++nt)
                    mma_f16(acc[mt][nt], ap[0], ap[1], ap[2], ap[3], b[2*nt], b[2*nt+1]);
            }
        }
        __syncthreads();
    }
    #pragma unroll
    for (int mt = 0; mt < 2; ++mt)
        #pragma unroll
        for (int nt = 0; nt < 8; ++nt) {
            int row = m0 + wm * 32 + mt * 16 + g;
            int col = n0 + wn * 64 + nt * 8 + 2 * cq;
            if (Cf) {
                float b0 = bias ? bias[col] : 0.f, b1 = bias ? bias[col + 1] : 0.f;
                *(float2*)(Cf + (size_t)row * DD + col) =
                    make_float2(acc[mt][nt][0] + b0, acc[mt][nt][1] + b1);
                *(float2*)(Cf + (size_t)(row + 8) * DD + col) =
                    make_float2(acc[mt][nt][2] + b0, acc[mt][nt][3] + b1);
            } else {
                *(unsigned*)(Ch + (size_t)row * DD + col) =
                    pack2h(acc[mt][nt][0], acc[mt][nt][1]);
                *(unsigned*)(Ch + (size_t)(row + 8) * DD + col) =
                    pack2h(acc[mt][nt][2], acc[mt][nt][3]);
            }
        }
}

// ===========================================================================
// Attention: CTA=(h, qtile 64, b). Flash, no-max softmax, fp16 in/out.
// Q/K/V fp16 via cp.async; K/V double-buffered. Warps 4(Mq)x2(Nk), tile 16x32.
// ===========================================================================
#define A_ST0 9216           // Q occupies [0, 9216)
#define A_STG 18432          // per stage: K 9216 + V 9216
#define A_LS  (A_ST0 + 2*A_STG)   // 46080
#define A_LI  (A_LS + 512)        // 46592
#define A_SM  (A_LI + 256)        // 46848
#define OPITCH 68

__global__ __launch_bounds__(256) void attn_mma(
    const __half* __restrict__ Q, const __half* __restrict__ K,
    const __half* __restrict__ V, const float* __restrict__ gprob,
    const int* __restrict__ mask, __half* __restrict__ X)
{
    extern __shared__ char sm[];
    float* LSM = (float*)(sm + A_LS);
    float* LIS = (float*)(sm + A_LI);
    float* OSM = (float*)sm;                   // reused after mainloop
    const unsigned sb = s2u(sm);

    const int tid = threadIdx.x, lane = tid & 31, wid = tid >> 5;
    const int wm = wid & 3, wn = wid >> 2;
    const int g = lane >> 2, cq = lane & 3;
    const int h = blockIdx.x, qt = blockIdx.y, b = blockIdx.z;
    const int q0 = qt * 64;

    const int aRow = lane & 15, aCol = (lane >> 4) << 3;
    const int bRow = (lane & 7) + ((lane >> 4) << 3), bCol = ((lane >> 3) & 1) << 3;
    const unsigned qHa = sb + ((wm*16 + aRow)*GP + aCol)*2;
    const unsigned kHb = sb + A_ST0 + ((wn*32 + bRow)*GP + bCol)*2, dK = 16*GPB;
    const unsigned vHb = sb + A_ST0 + 9216 + ((wn*32 + aRow)*GP + aCol)*2; // rows = k

    const size_t hb = (size_t)b * SS * DD + h * 64;
    const __half* Qb = Q + hb;
    const __half* Kb = K + hb;
    const __half* Vb = V + hb;

    auto issueKV = [&](int kt, int st) {
        const unsigned s0 = sb + A_ST0 + (unsigned)st * A_STG;
        const __half* Ksrc = Kb + (size_t)(kt * 64) * DD;
        const __half* Vsrc = Vb + (size_t)(kt * 64) * DD;
        #pragma unroll
        for (int u = 0; u < 2; ++u) {
            int c = tid + u * 256, row = c >> 3, off = c & 7;
            cpa16(s0 +        row*GPB + off*16, Ksrc + (size_t)row * DD + off * 8);
            cpa16(s0 + 9216 + row*GPB + off*16, Vsrc + (size_t)row * DD + off * 8);
        }
    };
    #pragma unroll
    for (int u = 0; u < 2; ++u) {               // Q tile 64x64 fp16
        int c = tid + u * 256, row = c >> 3, off = c & 7;
        cpa16(sb + row*GPB + off*16, Qb + (size_t)(q0 + row) * DD + off * 8);
    }
    issueKV(0, 0); CP_COMMIT();

    const int qg0 = q0 + wm * 16 + g, qg1 = qg0 + 8;
    const int*   mr0 = mask  + ((size_t)b * SS + qg0) * SS;
    const int*   mr1 = mask  + ((size_t)b * SS + qg1) * SS;
    const float* gr0 = gprob + ((size_t)b * SS + qg0) * SS;
    const float* gr1 = gprob + ((size_t)b * SS + qg1) * SS;

    float o[8][4] = {};
    float lsum0 = 0.f, lsum1 = 0.f;

    for (int kt = 0; kt < 16; ++kt) {
        if (kt < 15) { issueKV(kt + 1, (kt + 1) & 1); CP_COMMIT(); CP_WAIT(1); }
        else CP_WAIT(0);
        __syncthreads();
        const unsigned so = (unsigned)(kt & 1) * A_STG;
        const int k0 = kt * 64;

        // ---- S = Q.K^T (warp tile 16x32) ----
        float s[4][4] = {};
        #pragma unroll
        for (int kk = 0; kk < 4; ++kk) {
            const unsigned ko2 = kk * 32;
            unsigned aH[4], bh[8];
            ldm4(aH, qHa + ko2);
            ldm4(bh,     kHb + so + ko2); ldm4(bh + 4, kHb + so + dK + ko2);
            #pragma unroll
            for (int nt = 0; nt < 4; ++nt)
                mma_f16(s[nt], aH[0], aH[1], aH[2], aH[3], bh[2*nt], bh[2*nt+1]);
        }

        // ---- softmax numerator (no max-sub; masked -> exact 0); pack P fp16 ----
        unsigned PHf[4][2];
        #pragma unroll
        for (int nt = 0; nt < 4; ++nt) {
            const int kg = k0 + wn * 32 + nt * 8 + 2 * cq;
            int2   m0v = *(const int2*)(mr0 + kg);
            int2   m1v = *(const int2*)(mr1 + kg);
            float2 g0v = *(const float2*)(gr0 + kg);
            float2 g1v = *(const float2*)(gr1 + kg);
            float p00 = (m0v.x | (int)(kg     == qg0)) ? __expf(s[nt][0] * 0.125f) : 0.f;
            float p01 = (m0v.y | (int)(kg + 1 == qg0)) ? __expf(s[nt][1] * 0.125f) : 0.f;
            float p10 = (m1v.x | (int)(kg     == qg1)) ? __expf(s[nt][2] * 0.125f) : 0.f;
            float p11 = (m1v.y | (int)(kg + 1 == qg1)) ? __expf(s[nt][3] * 0.125f) : 0.f;
            lsum0 += p00 + p01;
            lsum1 += p10 + p11;
            PHf[nt][0] = pack2h(p00 * g0v.x, p01 * g0v.y);
            PHf[nt][1] = pack2h(p10 * g1v.x, p11 * g1v.y);
        }

        // ---- O_partial += P.V ; V B-frags via ldmatrix.trans ----
        #pragma unroll
        for (int kk2 = 0; kk2 < 2; ++kk2) {
            const unsigned kofs = so + (unsigned)kk2 * 16 * GPB;
            unsigned vh[16];
            #pragma unroll
            for (int dq = 0; dq < 4; ++dq)
                ldm4t(vh + dq * 4, vHb + kofs + dq * 32);
            unsigned p0 = PHf[2*kk2][0], p1 = PHf[2*kk2][1];
            unsigned p2 = PHf[2*kk2+1][0], p3 = PHf[2*kk2+1][1];
            #pragma unroll
            for (int dn = 0; dn < 8; ++dn)
                mma_f16(o[dn], p0, p1, p2, p3, vh[2*dn], vh[2*dn+1]);
        }
        __syncthreads();
    }

    // ---- epilogue: l reduce, O combine across wn, write fp16 X ----
    lsum0 += __shfl_xor_sync(0xFFFFFFFFu, lsum0, 1);
    lsum0 += __shfl_xor_sync(0xFFFFFFFFu, lsum0, 2);
    lsum1 += __shfl_xor_sync(0xFFFFFFFFu, lsum1, 1);
    lsum1 += __shfl_xor_sync(0xFFFFFFFFu, lsum1, 2);
    if (cq == 0) {
        LSM[wn * 64 + wm * 16 + g]     = lsum0;
        LSM[wn * 64 + wm * 16 + g + 8] = lsum1;
    }
    __syncthreads();
    if (tid < 64) LIS[tid] = 1.0f / (LSM[tid] + LSM[64 + tid]);
    if (wn == 0) {
        #pragma unroll
        for (int dn = 0; dn < 8; ++dn) {
            int r0 = wm * 16 + g, col = dn * 8 + 2 * cq;
            *(float2*)(OSM + r0 * OPITCH + col)       = make_float2(o[dn][0], o[dn][1]);
            *(float2*)(OSM + (r0 + 8) * OPITCH + col) = make_float2(o[dn][2], o[dn][3]);
        }
    }
    __syncthreads();
    if (wn == 1) {
        #pragma unroll
        for (int dn = 0; dn < 8; ++dn) {
            int r0 = wm * 16 + g, col = dn * 8 + 2 * cq;
            float2* p0 = (float2*)(OSM + r0 * OPITCH + col);
            float2* p1 = (float2*)(OSM + (r0 + 8) * OPITCH + col);
            p0->x += o[dn][0]; p0->y += o[dn][1];
            p1->x += o[dn][2]; p1->y += o[dn][3];
        }
    }
    __syncthreads();
    #pragma unroll
    for (int u = 0; u < 4; ++u) {
        int idx = tid + u * 256, rr = idx >> 4, c4 = idx & 15;
        float li = LIS[rr];
        float4 vv = *(float4*)(OSM + rr * OPITCH + c4 * 4);
        *(uint2*)(X + ((size_t)b * SS + q0 + rr) * DD + h * 64 + c4 * 4) =
            make_uint2(pack2h(vv.x * li, vv.y * li), pack2h(vv.z * li, vv.w * li));
    }
}

// ===========================================================================
extern "C" void kernel_launch(void* const* d_in, const int* in_sizes, int n_in,
                              void* d_out, int out_size)
{
    const float* query = (const float*)d_in[0];
    const float* key   = (const float*)d_in[1];
    const float* value = (const float*)d_in[2];
    const float* gprob = (const float*)d_in[3];
    const float* Wq    = (const float*)d_in[4];
    const float* Wk    = (const float*)d_in[5];
    const float* Wv    = (const float*)d_in[6];
    const float* Wh    = (const float*)d_in[7];
    const float* bh    = (const float*)d_in[8];
    const int*   mask  = (const int*)d_in[9];
    float* out = (float*)d_out;

    __half *Qh, *Kh, *Vh, *Xh;
    cudaGetSymbolAddress((void**)&Qh, g_Qh);
    cudaGetSymbolAddress((void**)&Kh, g_Kh);
    cudaGetSymbolAddress((void**)&Vh, g_Vh);
    cudaGetSymbolAddress((void**)&Xh, g_Xh);

    cudaFuncSetAttribute(gemm_mma<false>, cudaFuncAttributeMaxDynamicSharedMemorySize, G_SM);
    cudaFuncSetAttribute(gemm_mma<true>,  cudaFuncAttributeMaxDynamicSharedMemorySize, G_SM);
    cudaFuncSetAttribute(attn_mma, cudaFuncAttributeMaxDynamicSharedMemorySize, A_SM);

    dim3 blk(256);
    dim3 pg(DD / 128, NQ / 128);                // (4, 64)
    gemm_mma<false><<<pg, blk, G_SM>>>(query, nullptr, Wq, nullptr, nullptr, Qh);
    gemm_mma<false><<<pg, blk, G_SM>>>(key,   nullptr, Wk, nullptr, nullptr, Kh);
    gemm_mma<false><<<pg, blk, G_SM>>>(value, nullptr, Wv, nullptr, nullptr, Vh);
    attn_mma<<<dim3(HH, SS / 64, BBB), blk, A_SM>>>(Qh, Kh, Vh, gprob, mask, Xh);
    gemm_mma<true><<<pg, blk, G_SM>>>(nullptr, Xh, Wh, bh, out, nullptr);
}

// round 13
// speedup vs baseline: 1.3709x; 1.0425x over previous
#include <cuda_runtime.h>
#include <cuda_fp16.h>

#define SS 1024
#define DD 512
#define HH 8
#define BBB 8
#define NQ (BBB*SS)
#define ND (NQ*DD)
#define GP  72        // smem pitch in fp16 halves (144B rows -> conflict-free ldmatrix)
#define GPB 144

// fp16 scratch: projected Q,K,V and attention output X
__device__ __half g_Qh[ND];
__device__ __half g_Kh[ND];
__device__ __half g_Vh[ND];
__device__ __half g_Xh[ND];

// ---------------------------------------------------------------------------
__device__ __forceinline__ unsigned s2u(const void* p) {
    unsigned a;
    asm("{ .reg .u64 t; cvta.to.shared.u64 t, %1; cvt.u32.u64 %0, t; }" : "=r"(a) : "l"(p));
    return a;
}
__device__ __forceinline__ unsigned pack2h(float x0, float x1) {
    unsigned r;
    asm("cvt.rn.f16x2.f32 %0, %1, %2;" : "=r"(r) : "f"(x1), "f"(x0)); // low16=f16(x0)
    return r;
}
__device__ __forceinline__ void mma_f16(float c[4], unsigned a0, unsigned a1,
                                        unsigned a2, unsigned a3,
                                        unsigned b0, unsigned b1) {
    asm volatile("mma.sync.aligned.m16n8k16.row.col.f32.f16.f16.f32 "
        "{%0,%1,%2,%3}, {%4,%5,%6,%7}, {%8,%9}, {%0,%1,%2,%3};"
        : "+f"(c[0]), "+f"(c[1]), "+f"(c[2]), "+f"(c[3])
        : "r"(a0), "r"(a1), "r"(a2), "r"(a3), "r"(b0), "r"(b1));
}
__device__ __forceinline__ void ldm4(unsigned* r, unsigned addr) {
    asm volatile("ldmatrix.sync.aligned.m8n8.x4.shared.b16 {%0,%1,%2,%3}, [%4];"
        : "=r"(r[0]), "=r"(r[1]), "=r"(r[2]), "=r"(r[3]) : "r"(addr));
}
__device__ __forceinline__ void ldm4t(unsigned* r, unsigned addr) {
    asm volatile("ldmatrix.sync.aligned.m8n8.x4.trans.shared.b16 {%0,%1,%2,%3}, [%4];"
        : "=r"(r[0]), "=r"(r[1]), "=r"(r[2]), "=r"(r[3]) : "r"(addr));
}
__device__ __forceinline__ void cpa16(unsigned dst, const void* src) {
    asm volatile("cp.async.cg.shared.global [%0], [%1], 16;" :: "r"(dst), "l"(src));
}
#define CP_COMMIT() asm volatile("cp.async.commit_group;" ::: "memory")
#define CP_WAIT(n)  asm volatile("cp.async.wait_group %0;" :: "n"(n) : "memory")
// f32x4 -> fp16x4, one 8B store at [r][cbyte], pitch GPB
__device__ __forceinline__ void sts_h(char* base, int r, int cbyte, float4 v) {
    *(uint2*)(base + r*GPB + cbyte) = make_uint2(pack2h(v.x, v.y), pack2h(v.z, v.w));
}

#define G_AH 0
#define G_WH 18432
#define G_SM 36864

// ===========================================================================
// Merged projection GEMM: {Q,K,V}h[8192,512] = {query,key,value} @ W{q,k,v}^T
// grid (12, 64): blockIdx.x>>2 selects the matrix, (blockIdx.x&3)*128 = n0.
// CTA 128x128, warps 4(M)x2(N), warp tile 32x64.
// ===========================================================================
__global__ __launch_bounds__(256, 2) void gemm_proj(
    const float* __restrict__ inQ, const float* __restrict__ inK,
    const float* __restrict__ inV,
    const float* __restrict__ Wq, const float* __restrict__ Wk,
    const float* __restrict__ Wv,
    __half* __restrict__ Qo, __half* __restrict__ Ko, __half* __restrict__ Vo)
{
    extern __shared__ char sm[];
    char* AH = sm + G_AH;
    char* WH = sm + G_WH;
    const unsigned sb = s2u(sm);
    const int tid = threadIdx.x, lane = tid & 31, wid = tid >> 5;
    const int wm = wid & 3, wn = wid >> 2;
    const int g = lane >> 2, cq = lane & 3;
    const int which = blockIdx.x >> 2;
    const float* Af = (which == 0) ? inQ : (which == 1) ? inK : inV;
    const float* W  = (which == 0) ? Wq  : (which == 1) ? Wk  : Wv;
    __half* Ch      = (which == 0) ? Qo  : (which == 1) ? Ko  : Vo;
    const int m0 = blockIdx.y * 128, n0 = (blockIdx.x & 3) * 128;

    const int aRow = lane & 15, aCol = (lane >> 4) << 3;
    const int bRow = (lane & 7) + ((lane >> 4) << 3), bCol = ((lane >> 3) & 1) << 3;
    const unsigned aH0 = sb + G_AH + ((wm*32 + aRow)*GP + aCol)*2, dA = 16*GPB;
    const unsigned wH0 = sb + G_WH + ((wn*64 + bRow)*GP + bCol)*2;

    float acc[2][8][4] = {};

    for (int kc = 0; kc < 8; ++kc) {
        const int k0 = kc * 64;
        #pragma unroll
        for (int u = 0; u < 8; ++u) {               // A tile 128x64 f32
            int idx = tid + u * 256, rr = idx >> 4, c4 = idx & 15;
            float4 v = *(const float4*)(Af + (size_t)(m0 + rr) * DD + k0 + c4 * 4);
            sts_h(AH, rr, c4 * 8, v);
        }
        #pragma unroll
        for (int u = 0; u < 8; ++u) {               // W tile 128x64 f32
            int idx = tid + u * 256, rr = idx >> 4, c4 = idx & 15;
            float4 v = *(const float4*)(W + (size_t)(n0 + rr) * DD + k0 + c4 * 4);
            sts_h(WH, rr, c4 * 8, v);
        }
        __syncthreads();
        #pragma unroll
        for (int kk = 0; kk < 4; ++kk) {
            const unsigned ko2 = kk * 32;
            unsigned a[8], b[16];
            ldm4(a,     aH0 + ko2); ldm4(a + 4, aH0 + dA + ko2);
            #pragma unroll
            for (int nb = 0; nb < 4; ++nb)
                ldm4(b + 4*nb, wH0 + nb*dA + ko2);
            #pragma unroll
            for (int mt = 0; mt < 2; ++mt) {
                unsigned* ap = a + mt * 4;
                #pragma unroll
                for (int nt = 0; nt < 8; ++nt)
                    mma_f16(acc[mt][nt], ap[0], ap[1], ap[2], ap[3], b[2*nt], b[2*nt+1]);
            }
        }
        __syncthreads();
    }
    #pragma unroll
    for (int mt = 0; mt < 2; ++mt)
        #pragma unroll
        for (int nt = 0; nt < 8; ++nt) {
            int row = m0 + wm * 32 + mt * 16 + g;
            int col = n0 + wn * 64 + nt * 8 + 2 * cq;
            *(unsigned*)(Ch + (size_t)row * DD + col) =
                pack2h(acc[mt][nt][0], acc[mt][nt][1]);
            *(unsigned*)(Ch + (size_t)(row + 8) * DD + col) =
                pack2h(acc[mt][nt][2], acc[mt][nt][3]);
        }
}

// ===========================================================================
// Final GEMM: out[8192,512] = X(fp16) @ Wh^T + bh (f32 out)
// ===========================================================================
__global__ __launch_bounds__(256, 2) void gemm_final(
    const __half* __restrict__ Ah16, const float* __restrict__ W,
    const float* __restrict__ bias, float* __restrict__ Cf)
{
    extern __shared__ char sm[];
    char* WH = sm + G_WH;
    const unsigned sb = s2u(sm);
    const int tid = threadIdx.x, lane = tid & 31, wid = tid >> 5;
    const int wm = wid & 3, wn = wid >> 2;
    const int g = lane >> 2, cq = lane & 3;
    const int m0 = blockIdx.y * 128, n0 = blockIdx.x * 128;

    const int aRow = lane & 15, aCol = (lane >> 4) << 3;
    const int bRow = (lane & 7) + ((lane >> 4) << 3), bCol = ((lane >> 3) & 1) << 3;
    const unsigned aH0 = sb + G_AH + ((wm*32 + aRow)*GP + aCol)*2, dA = 16*GPB;
    const unsigned wH0 = sb + G_WH + ((wn*64 + bRow)*GP + bCol)*2;

    float acc[2][8][4] = {};

    for (int kc = 0; kc < 8; ++kc) {
        const int k0 = kc * 64;
        #pragma unroll
        for (int u = 0; u < 4; ++u) {               // A tile 128x64 fp16 via cp.async
            int c = tid + u * 256, row = c >> 3, off = c & 7;
            cpa16(sb + G_AH + row*GPB + off*16,
                  Ah16 + (size_t)(m0 + row) * DD + k0 + off * 8);
        }
        CP_COMMIT();
        #pragma unroll
        for (int u = 0; u < 8; ++u) {               // W tile 128x64 f32
            int idx = tid + u * 256, rr = idx >> 4, c4 = idx & 15;
            float4 v = *(const float4*)(W + (size_t)(n0 + rr) * DD + k0 + c4 * 4);
            sts_h(WH, rr, c4 * 8, v);
        }
        CP_WAIT(0);
        __syncthreads();
        #pragma unroll
        for (int kk = 0; kk < 4; ++kk) {
            const unsigned ko2 = kk * 32;
            unsigned a[8], b[16];
            ldm4(a,     aH0 + ko2); ldm4(a + 4, aH0 + dA + ko2);
            #pragma unroll
            for (int nb = 0; nb < 4; ++nb)
                ldm4(b + 4*nb, wH0 + nb*dA + ko2);
            #pragma unroll
            for (int mt = 0; mt < 2; ++mt) {
                unsigned* ap = a + mt * 4;
                #pragma unroll
                for (int nt = 0; nt < 8; ++nt)
                    mma_f16(acc[mt][nt], ap[0], ap[1], ap[2], ap[3], b[2*nt], b[2*nt+1]);
            }
        }
        __syncthreads();
    }
    #pragma unroll
    for (int mt = 0; mt < 2; ++mt)
        #pragma unroll
        for (int nt = 0; nt < 8; ++nt) {
            int row = m0 + wm * 32 + mt * 16 + g;
            int col = n0 + wn * 64 + nt * 8 + 2 * cq;
            float b0 = bias[col], b1 = bias[col + 1];
            *(float2*)(Cf + (size_t)row * DD + col) =
                make_float2(acc[mt][nt][0] + b0, acc[mt][nt][1] + b1);
            *(float2*)(Cf + (size_t)(row + 8) * DD + col) =
                make_float2(acc[mt][nt][2] + b0, acc[mt][nt][3] + b1);
        }
}

// ===========================================================================
// Attention: CTA=(h, qtile 64, b). Flash, no-max softmax, fp16 in/out.
// Q/K/V fp16 via cp.async; K/V double-buffered. 3 CTAs/SM (occupancy lever).
// ===========================================================================
#define A_ST0 9216           // Q occupies [0, 9216)
#define A_STG 18432          // per stage: K 9216 + V 9216
#define A_LS  (A_ST0 + 2*A_STG)   // 46080
#define A_LI  (A_LS + 512)        // 46592
#define A_SM  (A_LI + 256)        // 46848
#define OPITCH 68

__global__ __launch_bounds__(256, 3) void attn_mma(
    const __half* __restrict__ Q, const __half* __restrict__ K,
    const __half* __restrict__ V, const float* __restrict__ gprob,
    const int* __restrict__ mask, __half* __restrict__ X)
{
    extern __shared__ char sm[];
    float* LSM = (float*)(sm + A_LS);
    float* LIS = (float*)(sm + A_LI);
    float* OSM = (float*)sm;                   // reused after mainloop
    const unsigned sb = s2u(sm);

    const int tid = threadIdx.x, lane = tid & 31, wid = tid >> 5;
    const int wm = wid & 3, wn = wid >> 2;
    const int g = lane >> 2, cq = lane & 3;
    const int h = blockIdx.x, qt = blockIdx.y, b = blockIdx.z;
    const int q0 = qt * 64;

    const int aRow = lane & 15, aCol = (lane >> 4) << 3;
    const int bRow = (lane & 7) + ((lane >> 4) << 3), bCol = ((lane >> 3) & 1) << 3;
    const unsigned qHa = sb + ((wm*16 + aRow)*GP + aCol)*2;
    const unsigned kHb = sb + A_ST0 + ((wn*32 + bRow)*GP + bCol)*2, dK = 16*GPB;
    const unsigned vHb = sb + A_ST0 + 9216 + ((wn*32 + aRow)*GP + aCol)*2; // rows = k

    const size_t hb = (size_t)b * SS * DD + h * 64;
    const __half* Qb = Q + hb;
    const __half* Kb = K + hb;
    const __half* Vb = V + hb;

    auto issueKV = [&](int kt, int st) {
        const unsigned s0 = sb + A_ST0 + (unsigned)st * A_STG;
        const __half* Ksrc = Kb + (size_t)(kt * 64) * DD;
        const __half* Vsrc = Vb + (size_t)(kt * 64) * DD;
        #pragma unroll
        for (int u = 0; u < 2; ++u) {
            int c = tid + u * 256, row = c >> 3, off = c & 7;
            cpa16(s0 +        row*GPB + off*16, Ksrc + (size_t)row * DD + off * 8);
            cpa16(s0 + 9216 + row*GPB + off*16, Vsrc + (size_t)row * DD + off * 8);
        }
    };
    #pragma unroll
    for (int u = 0; u < 2; ++u) {               // Q tile 64x64 fp16
        int c = tid + u * 256, row = c >> 3, off = c & 7;
        cpa16(sb + row*GPB + off*16, Qb + (size_t)(q0 + row) * DD + off * 8);
    }
    issueKV(0, 0); CP_COMMIT();

    const int qg0 = q0 + wm * 16 + g, qg1 = qg0 + 8;
    const int*   mr0 = mask  + ((size_t)b * SS + qg0) * SS;
    const int*   mr1 = mask  + ((size_t)b * SS + qg1) * SS;
    const float* gr0 = gprob + ((size_t)b * SS + qg0) * SS;
    const float* gr1 = gprob + ((size_t)b * SS + qg1) * SS;

    float o[8][4] = {};
    float lsum0 = 0.f, lsum1 = 0.f;

    for (int kt = 0; kt < 16; ++kt) {
        if (kt < 15) { issueKV(kt + 1, (kt + 1) & 1); CP_COMMIT(); CP_WAIT(1); }
        else CP_WAIT(0);
        __syncthreads();
        const unsigned so = (unsigned)(kt & 1) * A_STG;
        const int k0 = kt * 64;

        // ---- S = Q.K^T (warp tile 16x32) ----
        float s[4][4] = {};
        #pragma unroll
        for (int kk = 0; kk < 4; ++kk) {
            const unsigned ko2 = kk * 32;
            unsigned aH[4], bh[8];
            ldm4(aH, qHa + ko2);
            ldm4(bh,     kHb + so + ko2); ldm4(bh + 4, kHb + so + dK + ko2);
            #pragma unroll
            for (int nt = 0; nt < 4; ++nt)
                mma_f16(s[nt], aH[0], aH[1], aH[2], aH[3], bh[2*nt], bh[2*nt+1]);
        }

        // ---- softmax numerator (no max-sub; masked -> exact 0); pack P fp16 ----
        unsigned PHf[4][2];
        #pragma unroll
        for (int nt = 0; nt < 4; ++nt) {
            const int kg = k0 + wn * 32 + nt * 8 + 2 * cq;
            int2   m0v = *(const int2*)(mr0 + kg);
            int2   m1v = *(const int2*)(mr1 + kg);
            float2 g0v = *(const float2*)(gr0 + kg);
            float2 g1v = *(const float2*)(gr1 + kg);
            float p00 = (m0v.x | (int)(kg     == qg0)) ? __expf(s[nt][0] * 0.125f) : 0.f;
            float p01 = (m0v.y | (int)(kg + 1 == qg0)) ? __expf(s[nt][1] * 0.125f) : 0.f;
            float p10 = (m1v.x | (int)(kg     == qg1)) ? __expf(s[nt][2] * 0.125f) : 0.f;
            float p11 = (m1v.y | (int)(kg + 1 == qg1)) ? __expf(s[nt][3] * 0.125f) : 0.f;
            lsum0 += p00 + p01;
            lsum1 += p10 + p11;
            PHf[nt][0] = pack2h(p00 * g0v.x, p01 * g0v.y);
            PHf[nt][1] = pack2h(p10 * g1v.x, p11 * g1v.y);
        }

        // ---- O_partial += P.V ; V B-frags via ldmatrix.trans ----
        #pragma unroll
        for (int kk2 = 0; kk2 < 2; ++kk2) {
            const unsigned kofs = so + (unsigned)kk2 * 16 * GPB;
            unsigned vh[16];
            #pragma unroll
            for (int dq = 0; dq < 4; ++dq)
                ldm4t(vh + dq * 4, vHb + kofs + dq * 32);
            unsigned p0 = PHf[2*kk2][0], p1 = PHf[2*kk2][1];
            unsigned p2 = PHf[2*kk2+1][0], p3 = PHf[2*kk2+1][1];
            #pragma unroll
            for (int dn = 0; dn < 8; ++dn)
                mma_f16(o[dn], p0, p1, p2, p3, vh[2*dn], vh[2*dn+1]);
        }
        __syncthreads();
    }

    // ---- epilogue: l reduce, O combine across wn, write fp16 X ----
    lsum0 += __shfl_xor_sync(0xFFFFFFFFu, lsum0, 1);
    lsum0 += __shfl_xor_sync(0xFFFFFFFFu, lsum0, 2);
    lsum1 += __shfl_xor_sync(0xFFFFFFFFu, lsum1, 1);
    lsum1 += __shfl_xor_sync(0xFFFFFFFFu, lsum1, 2);
    if (cq == 0) {
        LSM[wn * 64 + wm * 16 + g]     = lsum0;
        LSM[wn * 64 + wm * 16 + g + 8] = lsum1;
    }
    __syncthreads();
    if (tid < 64) LIS[tid] = 1.0f / (LSM[tid] + LSM[64 + tid]);
    if (wn == 0) {
        #pragma unroll
        for (int dn = 0; dn < 8; ++dn) {
            int r0 = wm * 16 + g, col = dn * 8 + 2 * cq;
            *(float2*)(OSM + r0 * OPITCH + col)       = make_float2(o[dn][0], o[dn][1]);
            *(float2*)(OSM + (r0 + 8) * OPITCH + col) = make_float2(o[dn][2], o[dn][3]);
        }
    }
    __syncthreads();
    if (wn == 1) {
        #pragma unroll
        for (int dn = 0; dn < 8; ++dn) {
            int r0 = wm * 16 + g, col = dn * 8 + 2 * cq;
            float2* p0 = (float2*)(OSM + r0 * OPITCH + col);
            float2* p1 = (float2*)(OSM + (r0 + 8) * OPITCH + col);
            p0->x += o[dn][0]; p0->y += o[dn][1];
            p1->x += o[dn][2]; p1->y += o[dn][3];
        }
    }
    __syncthreads();
    #pragma unroll
    for (int u = 0; u < 4; ++u) {
        int idx = tid + u * 256, rr = idx >> 4, c4 = idx & 15;
        float li = LIS[rr];
        float4 vv = *(float4*)(OSM + rr * OPITCH + c4 * 4);
        *(uint2*)(X + ((size_t)b * SS + q0 + rr) * DD + h * 64 + c4 * 4) =
            make_uint2(pack2h(vv.x * li, vv.y * li), pack2h(vv.z * li, vv.w * li));
    }
}

// ===========================================================================
extern "C" void kernel_launch(void* const* d_in, const int* in_sizes, int n_in,
                              void* d_out, int out_size)
{
    const float* query = (const float*)d_in[0];
    const float* key   = (const float*)d_in[1];
    const float* value = (const float*)d_in[2];
    const float* gprob = (const float*)d_in[3];
    const float* Wq    = (const float*)d_in[4];
    const float* Wk    = (const float*)d_in[5];
    const float* Wv    = (const float*)d_in[6];
    const float* Wh    = (const float*)d_in[7];
    const float* bh    = (const float*)d_in[8];
    const int*   mask  = (const int*)d_in[9];
    float* out = (float*)d_out;

    __half *Qh, *Kh, *Vh, *Xh;
    cudaGetSymbolAddress((void**)&Qh, g_Qh);
    cudaGetSymbolAddress((void**)&Kh, g_Kh);
    cudaGetSymbolAddress((void**)&Vh, g_Vh);
    cudaGetSymbolAddress((void**)&Xh, g_Xh);

    cudaFuncSetAttribute(gemm_proj,  cudaFuncAttributeMaxDynamicSharedMemorySize, G_SM);
    cudaFuncSetAttribute(gemm_final, cudaFuncAttributeMaxDynamicSharedMemorySize, G_SM);
    cudaFuncSetAttribute(attn_mma,   cudaFuncAttributeMaxDynamicSharedMemorySize, A_SM);

    dim3 blk(256);
    gemm_proj<<<dim3(12, 64), blk, G_SM>>>(query, key, value, Wq, Wk, Wv, Qh, Kh, Vh);
    attn_mma<<<dim3(HH, SS / 64, BBB), blk, A_SM>>>(Qh, Kh, Vh, gprob, mask, Xh);
    gemm_final<<<dim3(4, 64), blk, G_SM>>>(Xh, Wh, bh, out);
}

// round 14
// speedup vs baseline: 1.5644x; 1.1412x over previous
#include <cuda_runtime.h>
#include <cuda_fp16.h>

#define SS 1024
#define DD 512
#define HH 8
#define BBB 8
#define NQ (BBB*SS)
#define ND (NQ*DD)
#define GP  72        // smem pitch in fp16 halves (144B rows -> conflict-free ldmatrix)
#define GPB 144

// fp16 scratch: projected Q,K,V and attention output X
__device__ __half g_Qh[ND];
__device__ __half g_Kh[ND];
__device__ __half g_Vh[ND];
__device__ __half g_Xh[ND];

// ---------------------------------------------------------------------------
__device__ __forceinline__ unsigned s2u(const void* p) {
    unsigned a;
    asm("{ .reg .u64 t; cvta.to.shared.u64 t, %1; cvt.u32.u64 %0, t; }" : "=r"(a) : "l"(p));
    return a;
}
__device__ __forceinline__ unsigned pack2h(float x0, float x1) {
    unsigned r;
    asm("cvt.rn.f16x2.f32 %0, %1, %2;" : "=r"(r) : "f"(x1), "f"(x0)); // low16=f16(x0)
    return r;
}
__device__ __forceinline__ void mma_f16(float c[4], unsigned a0, unsigned a1,
                                        unsigned a2, unsigned a3,
                                        unsigned b0, unsigned b1) {
    asm volatile("mma.sync.aligned.m16n8k16.row.col.f32.f16.f16.f32 "
        "{%0,%1,%2,%3}, {%4,%5,%6,%7}, {%8,%9}, {%0,%1,%2,%3};"
        : "+f"(c[0]), "+f"(c[1]), "+f"(c[2]), "+f"(c[3])
        : "r"(a0), "r"(a1), "r"(a2), "r"(a3), "r"(b0), "r"(b1));
}
__device__ __forceinline__ void ldm4(unsigned* r, unsigned addr) {
    asm volatile("ldmatrix.sync.aligned.m8n8.x4.shared.b16 {%0,%1,%2,%3}, [%4];"
        : "=r"(r[0]), "=r"(r[1]), "=r"(r[2]), "=r"(r[3]) : "r"(addr));
}
__device__ __forceinline__ void ldm4t(unsigned* r, unsigned addr) {
    asm volatile("ldmatrix.sync.aligned.m8n8.x4.trans.shared.b16 {%0,%1,%2,%3}, [%4];"
        : "=r"(r[0]), "=r"(r[1]), "=r"(r[2]), "=r"(r[3]) : "r"(addr));
}
__device__ __forceinline__ void cpa16(unsigned dst, const void* src) {
    asm volatile("cp.async.cg.shared.global [%0], [%1], 16;" :: "r"(dst), "l"(src));
}
#define CP_COMMIT() asm volatile("cp.async.commit_group;" ::: "memory")
#define CP_WAIT(n)  asm volatile("cp.async.wait_group %0;" :: "n"(n) : "memory")
// f32x4 -> fp16x4, one 8B store at [r][cbyte], pitch GPB
__device__ __forceinline__ void sts_h(char* base, int r, int cbyte, float4 v) {
    *(uint2*)(base + r*GPB + cbyte) = make_uint2(pack2h(v.x, v.y), pack2h(v.z, v.w));
}

#define G_AH 0
#define G_WH 18432
#define G_SM 36864

// ===========================================================================
// Merged projection GEMM: {Q,K,V}h[8192,512] = {query,key,value} @ W{q,k,v}^T
// grid (12, 64): blockIdx.x>>2 selects the matrix, (blockIdx.x&3)*128 = n0.
// CTA 128x128, warps 4(M)x2(N), warp tile 32x64.   (unchanged from R13)
// ===========================================================================
__global__ __launch_bounds__(256, 2) void gemm_proj(
    const float* __restrict__ inQ, const float* __restrict__ inK,
    const float* __restrict__ inV,
    const float* __restrict__ Wq, const float* __restrict__ Wk,
    const float* __restrict__ Wv,
    __half* __restrict__ Qo, __half* __restrict__ Ko, __half* __restrict__ Vo)
{
    extern __shared__ char sm[];
    char* AH = sm + G_AH;
    char* WH = sm + G_WH;
    const unsigned sb = s2u(sm);
    const int tid = threadIdx.x, lane = tid & 31, wid = tid >> 5;
    const int wm = wid & 3, wn = wid >> 2;
    const int g = lane >> 2, cq = lane & 3;
    const int which = blockIdx.x >> 2;
    const float* Af = (which == 0) ? inQ : (which == 1) ? inK : inV;
    const float* W  = (which == 0) ? Wq  : (which == 1) ? Wk  : Wv;
    __half* Ch      = (which == 0) ? Qo  : (which == 1) ? Ko  : Vo;
    const int m0 = blockIdx.y * 128, n0 = (blockIdx.x & 3) * 128;

    const int aRow = lane & 15, aCol = (lane >> 4) << 3;
    const int bRow = (lane & 7) + ((lane >> 4) << 3), bCol = ((lane >> 3) & 1) << 3;
    const unsigned aH0 = sb + G_AH + ((wm*32 + aRow)*GP + aCol)*2, dA = 16*GPB;
    const unsigned wH0 = sb + G_WH + ((wn*64 + bRow)*GP + bCol)*2;

    float acc[2][8][4] = {};

    for (int kc = 0; kc < 8; ++kc) {
        const int k0 = kc * 64;
        #pragma unroll
        for (int u = 0; u < 8; ++u) {               // A tile 128x64 f32
            int idx = tid + u * 256, rr = idx >> 4, c4 = idx & 15;
            float4 v = *(const float4*)(Af + (size_t)(m0 + rr) * DD + k0 + c4 * 4);
            sts_h(AH, rr, c4 * 8, v);
        }
        #pragma unroll
        for (int u = 0; u < 8; ++u) {               // W tile 128x64 f32
            int idx = tid + u * 256, rr = idx >> 4, c4 = idx & 15;
            float4 v = *(const float4*)(W + (size_t)(n0 + rr) * DD + k0 + c4 * 4);
            sts_h(WH, rr, c4 * 8, v);
        }
        __syncthreads();
        #pragma unroll
        for (int kk = 0; kk < 4; ++kk) {
            const unsigned ko2 = kk * 32;
            unsigned a[8], b[16];
            ldm4(a,     aH0 + ko2); ldm4(a + 4, aH0 + dA + ko2);
            #pragma unroll
            for (int nb = 0; nb < 4; ++nb)
                ldm4(b + 4*nb, wH0 + nb*dA + ko2);
            #pragma unroll
            for (int mt = 0; mt < 2; ++mt) {
                unsigned* ap = a + mt * 4;
                #pragma unroll
                for (int nt = 0; nt < 8; ++nt)
                    mma_f16(acc[mt][nt], ap[0], ap[1], ap[2], ap[3], b[2*nt], b[2*nt+1]);
            }
        }
        __syncthreads();
    }
    #pragma unroll
    for (int mt = 0; mt < 2; ++mt)
        #pragma unroll
        for (int nt = 0; nt < 8; ++nt) {
            int row = m0 + wm * 32 + mt * 16 + g;
            int col = n0 + wn * 64 + nt * 8 + 2 * cq;
            *(unsigned*)(Ch + (size_t)row * DD + col) =
                pack2h(acc[mt][nt][0], acc[mt][nt][1]);
            *(unsigned*)(Ch + (size_t)(row + 8) * DD + col) =
                pack2h(acc[mt][nt][2], acc[mt][nt][3]);
        }
}

// ===========================================================================
// Final GEMM: out[8192,512] = X(fp16) @ Wh^T + bh (f32 out)  (unchanged)
// ===========================================================================
__global__ __launch_bounds__(256, 2) void gemm_final(
    const __half* __restrict__ Ah16, const float* __restrict__ W,
    const float* __restrict__ bias, float* __restrict__ Cf)
{
    extern __shared__ char sm[];
    char* WH = sm + G_WH;
    const unsigned sb = s2u(sm);
    const int tid = threadIdx.x, lane = tid & 31, wid = tid >> 5;
    const int wm = wid & 3, wn = wid >> 2;
    const int g = lane >> 2, cq = lane & 3;
    const int m0 = blockIdx.y * 128, n0 = blockIdx.x * 128;

    const int aRow = lane & 15, aCol = (lane >> 4) << 3;
    const int bRow = (lane & 7) + ((lane >> 4) << 3), bCol = ((lane >> 3) & 1) << 3;
    const unsigned aH0 = sb + G_AH + ((wm*32 + aRow)*GP + aCol)*2, dA = 16*GPB;
    const unsigned wH0 = sb + G_WH + ((wn*64 + bRow)*GP + bCol)*2;

    float acc[2][8][4] = {};

    for (int kc = 0; kc < 8; ++kc) {
        const int k0 = kc * 64;
        #pragma unroll
        for (int u = 0; u < 4; ++u) {               // A tile 128x64 fp16 via cp.async
            int c = tid + u * 256, row = c >> 3, off = c & 7;
            cpa16(sb + G_AH + row*GPB + off*16,
                  Ah16 + (size_t)(m0 + row) * DD + k0 + off * 8);
        }
        CP_COMMIT();
        #pragma unroll
        for (int u = 0; u < 8; ++u) {               // W tile 128x64 f32
            int idx = tid + u * 256, rr = idx >> 4, c4 = idx & 15;
            float4 v = *(const float4*)(W + (size_t)(n0 + rr) * DD + k0 + c4 * 4);
            sts_h(WH, rr, c4 * 8, v);
        }
        CP_WAIT(0);
        __syncthreads();
        #pragma unroll
        for (int kk = 0; kk < 4; ++kk) {
            const unsigned ko2 = kk * 32;
            unsigned a[8], b[16];
            ldm4(a,     aH0 + ko2); ldm4(a + 4, aH0 + dA + ko2);
            #pragma unroll
            for (int nb = 0; nb < 4; ++nb)
                ldm4(b + 4*nb, wH0 + nb*dA + ko2);
            #pragma unroll
            for (int mt = 0; mt < 2; ++mt) {
                unsigned* ap = a + mt * 4;
                #pragma unroll
                for (int nt = 0; nt < 8; ++nt)
                    mma_f16(acc[mt][nt], ap[0], ap[1], ap[2], ap[3], b[2*nt], b[2*nt+1]);
            }
        }
        __syncthreads();
    }
    #pragma unroll
    for (int mt = 0; mt < 2; ++mt)
        #pragma unroll
        for (int nt = 0; nt < 8; ++nt) {
            int row = m0 + wm * 32 + mt * 16 + g;
            int col = n0 + wn * 64 + nt * 8 + 2 * cq;
            float b0 = bias[col], b1 = bias[col + 1];
            *(float2*)(Cf + (size_t)row * DD + col) =
                make_float2(acc[mt][nt][0] + b0, acc[mt][nt][1] + b1);
            *(float2*)(Cf + (size_t)(row + 8) * DD + col) =
                make_float2(acc[mt][nt][2] + b0, acc[mt][nt][3] + b1);
        }
}

// ===========================================================================
// Attention: CTA=(h, qtile 32, b), 128 threads, warps 2(Mq)x2(Nk), tile 16x32.
// Smaller work quantum -> less wave-quantization tail. 5 CTAs/SM.
// Per-warp inner loop identical to R13.
// ===========================================================================
#define A_ST0 4608           // Q occupies [0, 4608): 32 rows x 144B
#define A_STG 18432          // per stage: K 9216 + V 9216
#define A_LS  (A_ST0 + 2*A_STG)   // 41472
#define A_LI  (A_LS + 256)        // LSM: 2x32 floats
#define A_SM  (A_LI + 128)        // 41856
#define OPITCH 68                 // OSM 32x68x4 = 8704B, overlays sm[0..]

__global__ __launch_bounds__(128, 5) void attn_mma(
    const __half* __restrict__ Q, const __half* __restrict__ K,
    const __half* __restrict__ V, const float* __restrict__ gprob,
    const int* __restrict__ mask, __half* __restrict__ X)
{
    extern __shared__ char sm[];
    float* LSM = (float*)(sm + A_LS);
    float* LIS = (float*)(sm + A_LI);
    float* OSM = (float*)sm;                   // reused after mainloop
    const unsigned sb = s2u(sm);

    const int tid = threadIdx.x, lane = tid & 31, wid = tid >> 5;
    const int wm = wid & 1, wn = wid >> 1;
    const int g = lane >> 2, cq = lane & 3;
    const int h = blockIdx.x, qt = blockIdx.y, b = blockIdx.z;
    const int q0 = qt * 32;

    const int aRow = lane & 15, aCol = (lane >> 4) << 3;
    const int bRow = (lane & 7) + ((lane >> 4) << 3), bCol = ((lane >> 3) & 1) << 3;
    const unsigned qHa = sb + ((wm*16 + aRow)*GP + aCol)*2;
    const unsigned kHb = sb + A_ST0 + ((wn*32 + bRow)*GP + bCol)*2, dK = 16*GPB;
    const unsigned vHb = sb + A_ST0 + 9216 + ((wn*32 + aRow)*GP + aCol)*2; // rows = k

    const size_t hb = (size_t)b * SS * DD + h * 64;
    const __half* Qb = Q + hb;
    const __half* Kb = K + hb;
    const __half* Vb = V + hb;

    auto issueKV = [&](int kt, int st) {
        const unsigned s0 = sb + A_ST0 + (unsigned)st * A_STG;
        const __half* Ksrc = Kb + (size_t)(kt * 64) * DD;
        const __half* Vsrc = Vb + (size_t)(kt * 64) * DD;
        #pragma unroll
        for (int u = 0; u < 4; ++u) {
            int c = tid + u * 128, row = c >> 3, off = c & 7;
            cpa16(s0 +        row*GPB + off*16, Ksrc + (size_t)row * DD + off * 8);
            cpa16(s0 + 9216 + row*GPB + off*16, Vsrc + (size_t)row * DD + off * 8);
        }
    };
    #pragma unroll
    for (int u = 0; u < 2; ++u) {               // Q tile 32x64 fp16
        int c = tid + u * 128, row = c >> 3, off = c & 7;
        cpa16(sb + row*GPB + off*16, Qb + (size_t)(q0 + row) * DD + off * 8);
    }
    issueKV(0, 0); CP_COMMIT();

    const int qg0 = q0 + wm * 16 + g, qg1 = qg0 + 8;
    const int*   mr0 = mask  + ((size_t)b * SS + qg0) * SS;
    const int*   mr1 = mask  + ((size_t)b * SS + qg1) * SS;
    const float* gr0 = gprob + ((size_t)b * SS + qg0) * SS;
    const float* gr1 = gprob + ((size_t)b * SS + qg1) * SS;

    float o[8][4] = {};
    float lsum0 = 0.f, lsum1 = 0.f;

    for (int kt = 0; kt < 16; ++kt) {
        if (kt < 15) { issueKV(kt + 1, (kt + 1) & 1); CP_COMMIT(); CP_WAIT(1); }
        else CP_WAIT(0);
        __syncthreads();
        const unsigned so = (unsigned)(kt & 1) * A_STG;
        const int k0 = kt * 64;

        // ---- S = Q.K^T (warp tile 16x32) ----
        float s[4][4] = {};
        #pragma unroll
        for (int kk = 0; kk < 4; ++kk) {
            const unsigned ko2 = kk * 32;
            unsigned aH[4], bh[8];
            ldm4(aH, qHa + ko2);
            ldm4(bh,     kHb + so + ko2); ldm4(bh + 4, kHb + so + dK + ko2);
            #pragma unroll
            for (int nt = 0; nt < 4; ++nt)
                mma_f16(s[nt], aH[0], aH[1], aH[2], aH[3], bh[2*nt], bh[2*nt+1]);
        }

        // ---- softmax numerator (no max-sub; masked -> exact 0); pack P fp16 ----
        unsigned PHf[4][2];
        #pragma unroll
        for (int nt = 0; nt < 4; ++nt) {
            const int kg = k0 + wn * 32 + nt * 8 + 2 * cq;
            int2   m0v = *(const int2*)(mr0 + kg);
            int2   m1v = *(const int2*)(mr1 + kg);
            float2 g0v = *(const float2*)(gr0 + kg);
            float2 g1v = *(const float2*)(gr1 + kg);
            float p00 = (m0v.x | (int)(kg     == qg0)) ? __expf(s[nt][0] * 0.125f) : 0.f;
            float p01 = (m0v.y | (int)(kg + 1 == qg0)) ? __expf(s[nt][1] * 0.125f) : 0.f;
            float p10 = (m1v.x | (int)(kg     == qg1)) ? __expf(s[nt][2] * 0.125f) : 0.f;
            float p11 = (m1v.y | (int)(kg + 1 == qg1)) ? __expf(s[nt][3] * 0.125f) : 0.f;
            lsum0 += p00 + p01;
            lsum1 += p10 + p11;
            PHf[nt][0] = pack2h(p00 * g0v.x, p01 * g0v.y);
            PHf[nt][1] = pack2h(p10 * g1v.x, p11 * g1v.y);
        }

        // ---- O_partial += P.V ; V B-frags via ldmatrix.trans ----
        #pragma unroll
        for (int kk2 = 0; kk2 < 2; ++kk2) {
            const unsigned kofs = so + (unsigned)kk2 * 16 * GPB;
            unsigned vh[16];
            #pragma unroll
            for (int dq = 0; dq < 4; ++dq)
                ldm4t(vh + dq * 4, vHb + kofs + dq * 32);
            unsigned p0 = PHf[2*kk2][0], p1 = PHf[2*kk2][1];
            unsigned p2 = PHf[2*kk2+1][0], p3 = PHf[2*kk2+1][1];
            #pragma unroll
            for (int dn = 0; dn < 8; ++dn)
                mma_f16(o[dn], p0, p1, p2, p3, vh[2*dn], vh[2*dn+1]);
        }
        __syncthreads();
    }

    // ---- epilogue: l reduce, O combine across wn, write fp16 X ----
    lsum0 += __shfl_xor_sync(0xFFFFFFFFu, lsum0, 1);
    lsum0 += __shfl_xor_sync(0xFFFFFFFFu, lsum0, 2);
    lsum1 += __shfl_xor_sync(0xFFFFFFFFu, lsum1, 1);
    lsum1 += __shfl_xor_sync(0xFFFFFFFFu, lsum1, 2);
    if (cq == 0) {
        LSM[wn * 32 + wm * 16 + g]     = lsum0;
        LSM[wn * 32 + wm * 16 + g + 8] = lsum1;
    }
    __syncthreads();
    if (tid < 32) LIS[tid] = 1.0f / (LSM[tid] + LSM[32 + tid]);
    if (wn == 0) {
        #pragma unroll
        for (int dn = 0; dn < 8; ++dn) {
            int r0 = wm * 16 + g, col = dn * 8 + 2 * cq;
            *(float2*)(OSM + r0 * OPITCH + col)       = make_float2(o[dn][0], o[dn][1]);
            *(float2*)(OSM + (r0 + 8) * OPITCH + col) = make_float2(o[dn][2], o[dn][3]);
        }
    }
    __syncthreads();
    if (wn == 1) {
        #pragma unroll
        for (int dn = 0; dn < 8; ++dn) {
            int r0 = wm * 16 + g, col = dn * 8 + 2 * cq;
            float2* p0 = (float2*)(OSM + r0 * OPITCH + col);
            float2* p1 = (float2*)(OSM + (r0 + 8) * OPITCH + col);
            p0->x += o[dn][0]; p0->y += o[dn][1];
            p1->x += o[dn][2]; p1->y += o[dn][3];
        }
    }
    __syncthreads();
    #pragma unroll
    for (int u = 0; u < 4; ++u) {
        int idx = tid + u * 128, rr = idx >> 4, c4 = idx & 15;
        float li = LIS[rr];
        float4 vv = *(float4*)(OSM + rr * OPITCH + c4 * 4);
        *(uint2*)(X + ((size_t)b * SS + q0 + rr) * DD + h * 64 + c4 * 4) =
            make_uint2(pack2h(vv.x * li, vv.y * li), pack2h(vv.z * li, vv.w * li));
    }
}

// ===========================================================================
extern "C" void kernel_launch(void* const* d_in, const int* in_sizes, int n_in,
                              void* d_out, int out_size)
{
    const float* query = (const float*)d_in[0];
    const float* key   = (const float*)d_in[1];
    const float* value = (const float*)d_in[2];
    const float* gprob = (const float*)d_in[3];
    const float* Wq    = (const float*)d_in[4];
    const float* Wk    = (const float*)d_in[5];
    const float* Wv    = (const float*)d_in[6];
    const float* Wh    = (const float*)d_in[7];
    const float* bh    = (const float*)d_in[8];
    const int*   mask  = (const int*)d_in[9];
    float* out = (float*)d_out;

    __half *Qh, *Kh, *Vh, *Xh;
    cudaGetSymbolAddress((void**)&Qh, g_Qh);
    cudaGetSymbolAddress((void**)&Kh, g_Kh);
    cudaGetSymbolAddress((void**)&Vh, g_Vh);
    cudaGetSymbolAddress((void**)&Xh, g_Xh);

    cudaFuncSetAttribute(gemm_proj,  cudaFuncAttributeMaxDynamicSharedMemorySize, G_SM);
    cudaFuncSetAttribute(gemm_final, cudaFuncAttributeMaxDynamicSharedMemorySize, G_SM);
    cudaFuncSetAttribute(attn_mma,   cudaFuncAttributeMaxDynamicSharedMemorySize, A_SM);

    gemm_proj<<<dim3(12, 64), 256, G_SM>>>(query, key, value, Wq, Wk, Wv, Qh, Kh, Vh);
    attn_mma<<<dim3(HH, SS / 32, BBB), 128, A_SM>>>(Qh, Kh, Vh, gprob, mask, Xh);
    gemm_final<<<dim3(4, 64), 256, G_SM>>>(Xh, Wh, bh, out);
}

// round 17
// speedup vs baseline: 1.6186x; 1.0347x over previous
#include <cuda_runtime.h>
#include <cuda_fp16.h>

#define SS 1024
#define DD 512
#define HH 8
#define BBB 8
#define NQ (BBB*SS)
#define ND (NQ*DD)
#define WD (DD*DD)
#define GP  72        // smem pitch in fp16 halves (144B rows -> conflict-free ldmatrix)
#define GPB 144

// fp16 scratch
__device__ __half g_Qh[ND];
__device__ __half g_Kh[ND];
__device__ __half g_Vh[ND];
__device__ __half g_Xh[ND];
__device__ __half g_Wh16[4*WD];    // Wq, Wk, Wv, Wh in fp16

// ---------------------------------------------------------------------------
__device__ __forceinline__ unsigned s2u(const void* p) {
    unsigned a;
    asm("{ .reg .u64 t; cvta.to.shared.u64 t, %1; cvt.u32.u64 %0, t; }" : "=r"(a) : "l"(p));
    return a;
}
__device__ __forceinline__ unsigned pack2h(float x0, float x1) {
    unsigned r;
    asm("cvt.rn.f16x2.f32 %0, %1, %2;" : "=r"(r) : "f"(x1), "f"(x0)); // low16=f16(x0)
    return r;
}
__device__ __forceinline__ void mma_f16(float c[4], unsigned a0, unsigned a1,
                                        unsigned a2, unsigned a3,
                                        unsigned b0, unsigned b1) {
    asm volatile("mma.sync.aligned.m16n8k16.row.col.f32.f16.f16.f32 "
        "{%0,%1,%2,%3}, {%4,%5,%6,%7}, {%8,%9}, {%0,%1,%2,%3};"
        : "+f"(c[0]), "+f"(c[1]), "+f"(c[2]), "+f"(c[3])
        : "r"(a0), "r"(a1), "r"(a2), "r"(a3), "r"(b0), "r"(b1));
}
__device__ __forceinline__ void ldm4(unsigned* r, unsigned addr) {
    asm volatile("ldmatrix.sync.aligned.m8n8.x4.shared.b16 {%0,%1,%2,%3}, [%4];"
        : "=r"(r[0]), "=r"(r[1]), "=r"(r[2]), "=r"(r[3]) : "r"(addr));
}
__device__ __forceinline__ void ldm4t(unsigned* r, unsigned addr) {
    asm volatile("ldmatrix.sync.aligned.m8n8.x4.trans.shared.b16 {%0,%1,%2,%3}, [%4];"
        : "=r"(r[0]), "=r"(r[1]), "=r"(r[2]), "=r"(r[3]) : "r"(addr));
}
__device__ __forceinline__ void cpa16(unsigned dst, const void* src) {
    asm volatile("cp.async.cg.shared.global [%0], [%1], 16;" :: "r"(dst), "l"(src));
}
#define CP_COMMIT() asm volatile("cp.async.commit_group;" ::: "memory")
#define CP_WAIT(n)  asm volatile("cp.async.wait_group %0;" :: "n"(n) : "memory")
__device__ __forceinline__ void sts_h(char* base, int r, int cbyte, float4 v) {
    *(uint2*)(base + r*GPB + cbyte) = make_uint2(pack2h(v.x, v.y), pack2h(v.z, v.w));
}

// ===========================================================================
// Weight f32 -> fp16, all four matrices. grid (WD/2048, 4), 256 thr.
// ===========================================================================
__global__ __launch_bounds__(256) void wcvt(
    const float* __restrict__ Wq, const float* __restrict__ Wk,
    const float* __restrict__ Wv, const float* __restrict__ Wh,
    __half* __restrict__ out)
{
    const int which = blockIdx.y;
    const float* W = (which == 0) ? Wq : (which == 1) ? Wk : (which == 2) ? Wv : Wh;
    int i = (blockIdx.x * 256 + threadIdx.x) * 2;       // 2 float4 = 8 elems
    const float4* src = (const float4*)W;
    float4 v0 = src[i], v1 = src[i + 1];
    uint4 o;
    o.x = pack2h(v0.x, v0.y); o.y = pack2h(v0.z, v0.w);
    o.z = pack2h(v1.x, v1.y); o.w = pack2h(v1.z, v1.w);
    *(uint4*)(out + (size_t)which * WD + i * 4) = o;
}

// ===========================================================================
// Merged projection GEMM: {Q,K,V}h = {query,key,value} @ W{q,k,v}^T
// W in fp16 (cp.async, double-buffered, P_SM = 55296 < 64KB). A f32 inline.
// grid (12, 64): blockIdx.x>>2 selects matrix, (blockIdx.x&3)*128 = n0.
// ===========================================================================
#define P_AH 0
#define P_W0 18432
#define P_SM 55296       // A 18432 + W stages 2x18432

__global__ __launch_bounds__(256, 2) void gemm_proj(
    const float* __restrict__ inQ, const float* __restrict__ inK,
    const float* __restrict__ inV, const __half* __restrict__ W16,
    __half* __restrict__ Qo, __half* __restrict__ Ko, __half* __restrict__ Vo)
{
    extern __shared__ char sm[];
    char* AH = sm + P_AH;
    const unsigned sb = s2u(sm);
    const int tid = threadIdx.x, lane = tid & 31, wid = tid >> 5;
    const int wm = wid & 3, wn = wid >> 2;
    const int g = lane >> 2, cq = lane & 3;
    const int which = blockIdx.x >> 2;
    const float* Af = (which == 0) ? inQ : (which == 1) ? inK : inV;
    const __half* W = W16 + (size_t)which * WD;
    __half* Ch      = (which == 0) ? Qo : (which == 1) ? Ko : Vo;
    const int m0 = blockIdx.y * 128, n0 = (blockIdx.x & 3) * 128;

    const int aRow = lane & 15, aCol = (lane >> 4) << 3;
    const int bRow = (lane & 7) + ((lane >> 4) << 3), bCol = ((lane >> 3) & 1) << 3;
    const unsigned aH0 = sb + P_AH + ((wm*32 + aRow)*GP + aCol)*2, dA = 16*GPB;
    const unsigned wH0 = sb + P_W0 + ((wn*64 + bRow)*GP + bCol)*2;

    auto issueW = [&](int kc, int st) {
        const unsigned s0 = sb + P_W0 + (unsigned)st * 18432;
        const __half* Wsrc = W + (size_t)n0 * DD + kc * 64;
        #pragma unroll
        for (int u = 0; u < 4; ++u) {
            int c = tid + u * 256, row = c >> 3, off = c & 7;
            cpa16(s0 + row*GPB + off*16, Wsrc + (size_t)row * DD + off * 8);
        }
    };

    float acc[2][8][4] = {};
    issueW(0, 0); CP_COMMIT();

    for (int kc = 0; kc < 8; ++kc) {
        const int k0 = kc * 64;
        #pragma unroll
        for (int u = 0; u < 8; ++u) {               // A tile 128x64 f32 (sync)
            int idx = tid + u * 256, rr = idx >> 4, c4 = idx & 15;
            float4 v = *(const float4*)(Af + (size_t)(m0 + rr) * DD + k0 + c4 * 4);
            sts_h(AH, rr, c4 * 8, v);
        }
        if (kc < 7) { issueW(kc + 1, (kc + 1) & 1); CP_COMMIT(); CP_WAIT(1); }
        else CP_WAIT(0);
        __syncthreads();
        const unsigned so = (unsigned)(kc & 1) * 18432;
        #pragma unroll
        for (int kk = 0; kk < 4; ++kk) {
            const unsigned ko2 = kk * 32;
            unsigned a[8], b[16];
            ldm4(a,     aH0 + ko2); ldm4(a + 4, aH0 + dA + ko2);
            #pragma unroll
            for (int nb = 0; nb < 4; ++nb)
                ldm4(b + 4*nb, wH0 + so + nb*dA + ko2);
            #pragma unroll
            for (int mt = 0; mt < 2; ++mt) {
                unsigned* ap = a + mt * 4;
                #pragma unroll
                for (int nt = 0; nt < 8; ++nt)
                    mma_f16(acc[mt][nt], ap[0], ap[1], ap[2], ap[3], b[2*nt], b[2*nt+1]);
            }
        }
        __syncthreads();
    }
    #pragma unroll
    for (int mt = 0; mt < 2; ++mt)
        #pragma unroll
        for (int nt = 0; nt < 8; ++nt) {
            int row = m0 + wm * 32 + mt * 16 + g;
            int col = n0 + wn * 64 + nt * 8 + 2 * cq;
            *(unsigned*)(Ch + (size_t)row * DD + col) =
                pack2h(acc[mt][nt][0], acc[mt][nt][1]);
            *(unsigned*)(Ch + (size_t)(row + 8) * DD + col) =
                pack2h(acc[mt][nt][2], acc[mt][nt][3]);
        }
}

// ===========================================================================
// Final GEMM: out = X(fp16) @ Wh16^T + bh.  R14-passing shell (G_SM 36864);
// W loader switched to cp.async of precomputed fp16 (fewer instructions).
// ===========================================================================
#define G_AH 0
#define G_WH 18432
#define G_SM 36864

__global__ __launch_bounds__(256, 2) void gemm_final(
    const __half* __restrict__ Ah16, const __half* __restrict__ W16,
    const float* __restrict__ bias, float* __restrict__ Cf)
{
    extern __shared__ char sm[];
    const unsigned sb = s2u(sm);
    const int tid = threadIdx.x, lane = tid & 31, wid = tid >> 5;
    const int wm = wid & 3, wn = wid >> 2;
    const int g = lane >> 2, cq = lane & 3;
    const int m0 = blockIdx.y * 128, n0 = blockIdx.x * 128;

    const int aRow = lane & 15, aCol = (lane >> 4) << 3;
    const int bRow = (lane & 7) + ((lane >> 4) << 3), bCol = ((lane >> 3) & 1) << 3;
    const unsigned aH0 = sb + G_AH + ((wm*32 + aRow)*GP + aCol)*2, dA = 16*GPB;
    const unsigned wH0 = sb + G_WH + ((wn*64 + bRow)*GP + bCol)*2;

    float acc[2][8][4] = {};

    for (int kc = 0; kc < 8; ++kc) {
        const int k0 = kc * 64;
        #pragma unroll
        for (int u = 0; u < 4; ++u) {               // A tile 128x64 fp16 via cp.async
            int c = tid + u * 256, row = c >> 3, off = c & 7;
            cpa16(sb + G_AH + row*GPB + off*16,
                  Ah16 + (size_t)(m0 + row) * DD + k0 + off * 8);
        }
        #pragma unroll
        for (int u = 0; u < 4; ++u) {               // W tile 128x64 fp16 via cp.async
            int c = tid + u * 256, row = c >> 3, off = c & 7;
            cpa16(sb + G_WH + row*GPB + off*16,
                  W16 + (size_t)(n0 + row) * DD + k0 + off * 8);
        }
        CP_COMMIT();
        CP_WAIT(0);
        __syncthreads();
        #pragma unroll
        for (int kk = 0; kk < 4; ++kk) {
            const unsigned ko2 = kk * 32;
            unsigned a[8], b[16];
            ldm4(a,     aH0 + ko2); ldm4(a + 4, aH0 + dA + ko2);
            #pragma unroll
            for (int nb = 0; nb < 4; ++nb)
                ldm4(b + 4*nb, wH0 + nb*dA + ko2);
            #pragma unroll
            for (int mt = 0; mt < 2; ++mt) {
                unsigned* ap = a + mt * 4;
                #pragma unroll
                for (int nt = 0; nt < 8; ++nt)
                    mma_f16(acc[mt][nt], ap[0], ap[1], ap[2], ap[3], b[2*nt], b[2*nt+1]);
            }
        }
        __syncthreads();
    }
    #pragma unroll
    for (int mt = 0; mt < 2; ++mt)
        #pragma unroll
        for (int nt = 0; nt < 8; ++nt) {
            int row = m0 + wm * 32 + mt * 16 + g;
            int col = n0 + wn * 64 + nt * 8 + 2 * cq;
            float b0 = bias[col], b1 = bias[col + 1];
            *(float2*)(Cf + (size_t)row * DD + col) =
                make_float2(acc[mt][nt][0] + b0, acc[mt][nt][1] + b1);
            *(float2*)(Cf + (size_t)(row + 8) * DD + col) =
                make_float2(acc[mt][nt][2] + b0, acc[mt][nt][3] + b1);
        }
}

// ===========================================================================
// Attention (unchanged from R14): CTA=(h, qtile 32, b), 128 thr, 2x2 warps.
// ===========================================================================
#define A_ST0 4608
#define A_STG 18432
#define A_LS  (A_ST0 + 2*A_STG)
#define A_LI  (A_LS + 256)
#define A_SM  (A_LI + 128)
#define OPITCH 68

__global__ __launch_bounds__(128, 5) void attn_mma(
    const __half* __restrict__ Q, const __half* __restrict__ K,
    const __half* __restrict__ V, const float* __restrict__ gprob,
    const int* __restrict__ mask, __half* __restrict__ X)
{
    extern __shared__ char sm[];
    float* LSM = (float*)(sm + A_LS);
    float* LIS = (float*)(sm + A_LI);
    float* OSM = (float*)sm;
    const unsigned sb = s2u(sm);

    const int tid = threadIdx.x, lane = tid & 31, wid = tid >> 5;
    const int wm = wid & 1, wn = wid >> 1;
    const int g = lane >> 2, cq = lane & 3;
    const int h = blockIdx.x, qt = blockIdx.y, b = blockIdx.z;
    const int q0 = qt * 32;

    const int aRow = lane & 15, aCol = (lane >> 4) << 3;
    const int bRow = (lane & 7) + ((lane >> 4) << 3), bCol = ((lane >> 3) & 1) << 3;
    const unsigned qHa = sb + ((wm*16 + aRow)*GP + aCol)*2;
    const unsigned kHb = sb + A_ST0 + ((wn*32 + bRow)*GP + bCol)*2, dK = 16*GPB;
    const unsigned vHb = sb + A_ST0 + 9216 + ((wn*32 + aRow)*GP + aCol)*2;

    const size_t hb = (size_t)b * SS * DD + h * 64;
    const __half* Qb = Q + hb;
    const __half* Kb = K + hb;
    const __half* Vb = V + hb;

    auto issueKV = [&](int kt, int st) {
        const unsigned s0 = sb + A_ST0 + (unsigned)st * A_STG;
        const __half* Ksrc = Kb + (size_t)(kt * 64) * DD;
        const __half* Vsrc = Vb + (size_t)(kt * 64) * DD;
        #pragma unroll
        for (int u = 0; u < 4; ++u) {
            int c = tid + u * 128, row = c >> 3, off = c & 7;
            cpa16(s0 +        row*GPB + off*16, Ksrc + (size_t)row * DD + off * 8);
            cpa16(s0 + 9216 + row*GPB + off*16, Vsrc + (size_t)row * DD + off * 8);
        }
    };
    #pragma unroll
    for (int u = 0; u < 2; ++u) {
        int c = tid + u * 128, row = c >> 3, off = c & 7;
        cpa16(sb + row*GPB + off*16, Qb + (size_t)(q0 + row) * DD + off * 8);
    }
    issueKV(0, 0); CP_COMMIT();

    const int qg0 = q0 + wm * 16 + g, qg1 = qg0 + 8;
    const int*   mr0 = mask  + ((size_t)b * SS + qg0) * SS;
    const int*   mr1 = mask  + ((size_t)b * SS + qg1) * SS;
    const float* gr0 = gprob + ((size_t)b * SS + qg0) * SS;
    const float* gr1 = gprob + ((size_t)b * SS + qg1) * SS;

    float o[8][4] = {};
    float lsum0 = 0.f, lsum1 = 0.f;

    for (int kt = 0; kt < 16; ++kt) {
        if (kt < 15) { issueKV(kt + 1, (kt + 1) & 1); CP_COMMIT(); CP_WAIT(1); }
        else CP_WAIT(0);
        __syncthreads();
        const unsigned so = (unsigned)(kt & 1) * A_STG;
        const int k0 = kt * 64;

        float s[4][4] = {};
        #pragma unroll
        for (int kk = 0; kk < 4; ++kk) {
            const unsigned ko2 = kk * 32;
            unsigned aH[4], bh[8];
            ldm4(aH, qHa + ko2);
            ldm4(bh,     kHb + so + ko2); ldm4(bh + 4, kHb + so + dK + ko2);
            #pragma unroll
            for (int nt = 0; nt < 4; ++nt)
                mma_f16(s[nt], aH[0], aH[1], aH[2], aH[3], bh[2*nt], bh[2*nt+1]);
        }

        unsigned PHf[4][2];
        #pragma unroll
        for (int nt = 0; nt < 4; ++nt) {
            const int kg = k0 + wn * 32 + nt * 8 + 2 * cq;
            int2   m0v = *(const int2*)(mr0 + kg);
            int2   m1v = *(const int2*)(mr1 + kg);
            float2 g0v = *(const float2*)(gr0 + kg);
            float2 g1v = *(const float2*)(gr1 + kg);
            float p00 = (m0v.x | (int)(kg     == qg0)) ? __expf(s[nt][0] * 0.125f) : 0.f;
            float p01 = (m0v.y | (int)(kg + 1 == qg0)) ? __expf(s[nt][1] * 0.125f) : 0.f;
            float p10 = (m1v.x | (int)(kg     == qg1)) ? __expf(s[nt][2] * 0.125f) : 0.f;
            float p11 = (m1v.y | (int)(kg + 1 == qg1)) ? __expf(s[nt][3] * 0.125f) : 0.f;
            lsum0 += p00 + p01;
            lsum1 += p10 + p11;
            PHf[nt][0] = pack2h(p00 * g0v.x, p01 * g0v.y);
            PHf[nt][1] = pack2h(p10 * g1v.x, p11 * g1v.y);
        }

        #pragma unroll
        for (int kk2 = 0; kk2 < 2; ++kk2) {
            const unsigned kofs = so + (unsigned)kk2 * 16 * GPB;
            unsigned vh[16];
            #pragma unroll
            for (int dq = 0; dq < 4; ++dq)
                ldm4t(vh + dq * 4, vHb + kofs + dq * 32);
            unsigned p0 = PHf[2*kk2][0], p1 = PHf[2*kk2][1];
            unsigned p2 = PHf[2*kk2+1][0], p3 = PHf[2*kk2+1][1];
            #pragma unroll
            for (int dn = 0; dn < 8; ++dn)
                mma_f16(o[dn], p0, p1, p2, p3, vh[2*dn], vh[2*dn+1]);
        }
        __syncthreads();
    }

    lsum0 += __shfl_xor_sync(0xFFFFFFFFu, lsum0, 1);
    lsum0 += __shfl_xor_sync(0xFFFFFFFFu, lsum0, 2);
    lsum1 += __shfl_xor_sync(0xFFFFFFFFu, lsum1, 1);
    lsum1 += __shfl_xor_sync(0xFFFFFFFFu, lsum1, 2);
    if (cq == 0) {
        LSM[wn * 32 + wm * 16 + g]     = lsum0;
        LSM[wn * 32 + wm * 16 + g + 8] = lsum1;
    }
    __syncthreads();
    if (tid < 32) LIS[tid] = 1.0f / (LSM[tid] + LSM[32 + tid]);
    if (wn == 0) {
        #pragma unroll
        for (int dn = 0; dn < 8; ++dn) {
            int r0 = wm * 16 + g, col = dn * 8 + 2 * cq;
            *(float2*)(OSM + r0 * OPITCH + col)       = make_float2(o[dn][0], o[dn][1]);
            *(float2*)(OSM + (r0 + 8) * OPITCH + col) = make_float2(o[dn][2], o[dn][3]);
        }
    }
    __syncthreads();
    if (wn == 1) {
        #pragma unroll
        for (int dn = 0; dn < 8; ++dn) {
            int r0 = wm * 16 + g, col = dn * 8 + 2 * cq;
            float2* p0 = (float2*)(OSM + r0 * OPITCH + col);
            float2* p1 = (float2*)(OSM + (r0 + 8) * OPITCH + col);
            p0->x += o[dn][0]; p0->y += o[dn][1];
            p1->x += o[dn][2]; p1->y += o[dn][3];
        }
    }
    __syncthreads();
    #pragma unroll
    for (int u = 0; u < 4; ++u) {
        int idx = tid + u * 128, rr = idx >> 4, c4 = idx & 15;
        float li = LIS[rr];
        float4 vv = *(float4*)(OSM + rr * OPITCH + c4 * 4);
        *(uint2*)(X + ((size_t)b * SS + q0 + rr) * DD + h * 64 + c4 * 4) =
            make_uint2(pack2h(vv.x * li, vv.y * li), pack2h(vv.z * li, vv.w * li));
    }
}

// ===========================================================================
extern "C" void kernel_launch(void* const* d_in, const int* in_sizes, int n_in,
                              void* d_out, int out_size)
{
    const float* query = (const float*)d_in[0];
    const float* key   = (const float*)d_in[1];
    const float* value = (const float*)d_in[2];
    const float* gprob = (const float*)d_in[3];
    const float* Wq    = (const float*)d_in[4];
    const float* Wk    = (const float*)d_in[5];
    const float* Wv    = (const float*)d_in[6];
    const float* Wh    = (const float*)d_in[7];
    const float* bh    = (const float*)d_in[8];
    const int*   mask  = (const int*)d_in[9];
    float* out = (float*)d_out;

    __half *Qh, *Kh, *Vh, *Xh, *Wh16;
    cudaGetSymbolAddress((void**)&Qh, g_Qh);
    cudaGetSymbolAddress((void**)&Kh, g_Kh);
    cudaGetSymbolAddress((void**)&Vh, g_Vh);
    cudaGetSymbolAddress((void**)&Xh, g_Xh);
    cudaGetSymbolAddress((void**)&Wh16, g_Wh16);

    cudaFuncSetAttribute(gemm_proj,  cudaFuncAttributeMaxDynamicSharedMemorySize, P_SM);
    cudaFuncSetAttribute(gemm_final, cudaFuncAttributeMaxDynamicSharedMemorySize, G_SM);
    cudaFuncSetAttribute(attn_mma,   cudaFuncAttributeMaxDynamicSharedMemorySize, A_SM);

    wcvt<<<dim3(WD/2048, 4), 256>>>(Wq, Wk, Wv, Wh, Wh16);
    gemm_proj<<<dim3(12, 64), 256, P_SM>>>(query, key, value, Wh16, Qh, Kh, Vh);
    attn_mma<<<dim3(HH, SS / 32, BBB), 128, A_SM>>>(Qh, Kh, Vh, gprob, mask, Xh);
    gemm_final<<<dim3(4, 64), 256, G_SM>>>(Xh, Wh16 + 3*(size_t)WD, bh, out);
}